// round 1
// baseline (speedup 1.0000x reference)
#include <cuda_runtime.h>
#include <cstddef>

// Problem dims (compile-time)
#define Bb   4
#define Ss   2048
#define DIN  512
#define Hh   8
#define DKk  64
#define DM   512               // H * DK
#define MROWS (Bb*Ss)          // 8192

// Scratch (device globals: allocation-free rule)
__device__ float g_Q [MROWS*DM];
__device__ float g_K [MROWS*DM];
__device__ float g_V [MROWS*DM];
__device__ float g_AO[MROWS*DM];
__device__ float g_P [MROWS*DIN];

// ---------------------------------------------------------------------------
// GEMM: C[M,512] = X[M,512] @ W[512,512] + bias   (BM=64, BN=64, BK=16, 4x4/thr)
// ---------------------------------------------------------------------------
__global__ __launch_bounds__(256)
void gemm_bias_kernel(const float* __restrict__ X, const float* __restrict__ W,
                      const float* __restrict__ bias, float* __restrict__ C) {
    __shared__ float Xs[64][17];
    __shared__ float Ws[16][64];
    const int tid = threadIdx.x;
    const int tx = tid & 15, ty = tid >> 4;
    const int bm = blockIdx.x * 64;
    const int bn = blockIdx.y * 64;

    float acc[4][4] = {};

    for (int k0 = 0; k0 < 512; k0 += 16) {
        #pragma unroll
        for (int l = 0; l < 4; l++) {
            int e = tid + l * 256;
            int r = e >> 4, c = e & 15;
            Xs[r][c] = X[(size_t)(bm + r) * 512 + k0 + c];
        }
        #pragma unroll
        for (int l = 0; l < 4; l++) {
            int e = tid + l * 256;
            int r = e >> 6, c = e & 63;
            Ws[r][c] = W[(size_t)(k0 + r) * 512 + bn + c];
        }
        __syncthreads();
        #pragma unroll
        for (int k = 0; k < 16; k++) {
            float a[4], bvv[4];
            #pragma unroll
            for (int i = 0; i < 4; i++) a[i] = Xs[ty * 4 + i][k];
            #pragma unroll
            for (int j = 0; j < 4; j++) bvv[j] = Ws[k][tx * 4 + j];
            #pragma unroll
            for (int i = 0; i < 4; i++)
                #pragma unroll
                for (int j = 0; j < 4; j++)
                    acc[i][j] += a[i] * bvv[j];
        }
        __syncthreads();
    }

    #pragma unroll
    for (int i = 0; i < 4; i++) {
        int row = bm + ty * 4 + i;
        #pragma unroll
        for (int j = 0; j < 4; j++) {
            int col = bn + tx * 4 + j;
            C[(size_t)row * 512 + col] = acc[i][j] + bias[col];
        }
    }
}

// ---------------------------------------------------------------------------
// Attention: per (b,h), 64 query rows per block, online softmax over 32-key tiles.
// scores = (Q.K^T/8) * mask ; scores = scores>0 ? scores : -1e4 ; softmax ; @V
// ---------------------------------------------------------------------------
__global__ __launch_bounds__(256)
void attn_kernel(const float* __restrict__ mask) {
    __shared__ float Qs [64][65];
    __shared__ float KVs[32][65];
    __shared__ float Ps [64][33];
    __shared__ float row_m[64], row_l[64], row_f[64];

    const int tid = threadIdx.x;
    const int bh  = blockIdx.y;            // b*H + h
    const int b   = bh / Hh;
    const int h   = bh % Hh;
    const int q0  = blockIdx.x * 64;

    const float* Qb = g_Q + (size_t)b * Ss * 512 + h * 64;
    const float* Kb = g_K + (size_t)b * Ss * 512 + h * 64;
    const float* Vb = g_V + (size_t)b * Ss * 512 + h * 64;
    const float* Mb = mask + (size_t)b * Ss * Ss;

    // Load Q tile (64x64)
    #pragma unroll
    for (int l = 0; l < 16; l++) {
        int e = tid + l * 256;
        int r = e >> 6, c = e & 63;
        Qs[r][c] = Qb[(size_t)(q0 + r) * 512 + c];
    }
    if (tid < 64) { row_m[tid] = -1e30f; row_l[tid] = 0.f; }
    __syncthreads();

    const int ty = tid >> 4, tx = tid & 15;     // score mapping: 4 rows x 2 cols
    const int qi_av = tid >> 2;                 // AV mapping: 4 threads / row
    const int d0    = (tid & 3) * 16;

    float O[16];
    #pragma unroll
    for (int i = 0; i < 16; i++) O[i] = 0.f;

    for (int kt = 0; kt < Ss / 32; kt++) {
        const int k0 = kt * 32;

        // Load K tile (32x64)
        #pragma unroll
        for (int l = 0; l < 8; l++) {
            int e = tid + l * 256;
            int r = e >> 6, c = e & 63;
            KVs[r][c] = Kb[(size_t)(k0 + r) * 512 + c];
        }
        __syncthreads();

        // Scores (each thread: 4 rows x 2 cols)
        #pragma unroll
        for (int i = 0; i < 4; i++) {
            const int qi = ty * 4 + i;
            #pragma unroll
            for (int j = 0; j < 2; j++) {
                const int kj = tx * 2 + j;
                float s = 0.f;
                #pragma unroll
                for (int d = 0; d < 64; d++) s += Qs[qi][d] * KVs[kj][d];
                s *= 0.125f;
                s *= Mb[(size_t)(q0 + qi) * Ss + k0 + kj];
                s = (s > 0.f) ? s : -10000.f;
                Ps[qi][kj] = s;
            }
        }
        __syncthreads();

        // Load V tile into same smem; threads<64 do online-softmax row stats
        #pragma unroll
        for (int l = 0; l < 8; l++) {
            int e = tid + l * 256;
            int r = e >> 6, c = e & 63;
            KVs[r][c] = Vb[(size_t)(k0 + r) * 512 + c];
        }
        if (tid < 64) {
            float m_old = row_m[tid];
            float m_new = m_old;
            #pragma unroll
            for (int kj = 0; kj < 32; kj++) m_new = fmaxf(m_new, Ps[tid][kj]);
            float f = __expf(m_old - m_new);
            float l_new = row_l[tid] * f;
            #pragma unroll
            for (int kj = 0; kj < 32; kj++) {
                float p = __expf(Ps[tid][kj] - m_new);
                Ps[tid][kj] = p;
                l_new += p;
            }
            row_m[tid] = m_new; row_l[tid] = l_new; row_f[tid] = f;
        }
        __syncthreads();

        // AV accumulate
        const float f = row_f[qi_av];
        #pragma unroll
        for (int i = 0; i < 16; i++) O[i] *= f;
        #pragma unroll
        for (int kj = 0; kj < 32; kj++) {
            const float p = Ps[qi_av][kj];
            #pragma unroll
            for (int i = 0; i < 16; i++) O[i] += p * KVs[kj][d0 + i];
        }
        __syncthreads();
    }

    const float inv_l = 1.f / row_l[qi_av];
    float* AOb = g_AO + (size_t)b * Ss * 512 + h * 64;
    #pragma unroll
    for (int i = 0; i < 16; i++)
        AOb[(size_t)(q0 + qi_av) * 512 + d0 + i] = O[i] * inv_l;
}

// ---------------------------------------------------------------------------
// Residual + LayerNorm: out = LN(q + g_P) * gamma + beta   (one block per row)
// ---------------------------------------------------------------------------
__global__ __launch_bounds__(512)
void ln_kernel(const float* __restrict__ q, const float* __restrict__ gamma,
               const float* __restrict__ beta, float* __restrict__ out) {
    __shared__ float rs[16], rs2[16];
    const int r = blockIdx.x;
    const int j = threadIdx.x;

    const float v = q[(size_t)r * 512 + j] + g_P[(size_t)r * 512 + j];

    float s = v, s2 = v * v;
    #pragma unroll
    for (int o = 16; o > 0; o >>= 1) {
        s  += __shfl_xor_sync(0xffffffffu, s,  o);
        s2 += __shfl_xor_sync(0xffffffffu, s2, o);
    }
    const int w = j >> 5, ln = j & 31;
    if (ln == 0) { rs[w] = s; rs2[w] = s2; }
    __syncthreads();
    if (w == 0) {
        s  = (ln < 16) ? rs[ln]  : 0.f;
        s2 = (ln < 16) ? rs2[ln] : 0.f;
        #pragma unroll
        for (int o = 8; o > 0; o >>= 1) {
            s  += __shfl_xor_sync(0xffffffffu, s,  o);
            s2 += __shfl_xor_sync(0xffffffffu, s2, o);
        }
        if (ln == 0) { rs[0] = s; rs2[0] = s2; }
    }
    __syncthreads();

    const float mu  = rs[0] * (1.f / 512.f);
    const float var = rs2[0] * (1.f / 512.f) - mu * mu;
    const float inv = rsqrtf(var + 1e-5f);
    out[(size_t)r * 512 + j] = (v - mu) * inv * gamma[j] + beta[j];
}

// ---------------------------------------------------------------------------
extern "C" void kernel_launch(void* const* d_in, const int* in_sizes, int n_in,
                              void* d_out, int out_size) {
    const float* q     = (const float*)d_in[0];
    const float* k     = (const float*)d_in[1];
    const float* v     = (const float*)d_in[2];
    const float* mask  = (const float*)d_in[3];
    const float* Wq    = (const float*)d_in[4];
    const float* bq    = (const float*)d_in[5];
    const float* Wk    = (const float*)d_in[6];
    const float* bk    = (const float*)d_in[7];
    const float* Wv    = (const float*)d_in[8];
    const float* bv    = (const float*)d_in[9];
    const float* Wo    = (const float*)d_in[10];
    const float* bo    = (const float*)d_in[11];
    const float* gamma = (const float*)d_in[12];
    const float* beta  = (const float*)d_in[13];
    float* out = (float*)d_out;

    float *gQ, *gK, *gV, *gAO, *gP;
    cudaGetSymbolAddress((void**)&gQ,  g_Q);
    cudaGetSymbolAddress((void**)&gK,  g_K);
    cudaGetSymbolAddress((void**)&gV,  g_V);
    cudaGetSymbolAddress((void**)&gAO, g_AO);
    cudaGetSymbolAddress((void**)&gP,  g_P);

    dim3 gg(MROWS / 64, 512 / 64);
    gemm_bias_kernel<<<gg, 256>>>(q, Wq, bq, gQ);
    gemm_bias_kernel<<<gg, 256>>>(k, Wk, bk, gK);
    gemm_bias_kernel<<<gg, 256>>>(v, Wv, bv, gV);

    attn_kernel<<<dim3(Ss / 64, Bb * Hh), 256>>>(mask);

    gemm_bias_kernel<<<gg, 256>>>(gAO, Wo, bo, gP);

    ln_kernel<<<MROWS, 512>>>(q, gamma, beta, out);
}

// round 2
// speedup vs baseline: 2.7198x; 2.7198x over previous
#include <cuda_runtime.h>
#include <cstddef>

#define Bb   4
#define Ss   2048
#define DIN  512
#define Hh   8
#define DKk  64
#define DM   512
#define MROWS (Bb*Ss)          // 8192

// Scratch (device globals: allocation-free rule)
__device__ float g_Q [MROWS*DM];
__device__ float g_K [MROWS*DM];
__device__ float g_V [MROWS*DM];
__device__ float g_AO[MROWS*DM];
__device__ float g_P [MROWS*DIN];

// ---------------------------------------------------------------------------
// GEMM: C[M,512] = X[M,512] @ W[512,512] + bias
// BM=128, BN=64, BK=16, 256 threads, 8x4 fragment per thread.
// ---------------------------------------------------------------------------
__global__ __launch_bounds__(256)
void gemm_bias_kernel(const float* __restrict__ X, const float* __restrict__ W,
                      const float* __restrict__ bias, float* __restrict__ C) {
    __shared__ float As[128][17];   // [m][k], pad 1
    __shared__ float Bs[16][68];    // [k][n], pad 4 (float4-aligned)

    const int tid = threadIdx.x;
    const int tx = tid & 15;        // n-dir (4 cols each)
    const int ty = tid >> 4;        // m-dir (8 rows each)
    const int bm = blockIdx.x * 128;
    const int bn = blockIdx.y * 64;

    float acc[8][4];
    #pragma unroll
    for (int i = 0; i < 8; i++)
        #pragma unroll
        for (int j = 0; j < 4; j++) acc[i][j] = 0.f;

    for (int k0 = 0; k0 < 512; k0 += 16) {
        // Load X tile 128x16 (512 float4, 2/thread)
        #pragma unroll
        for (int l = 0; l < 2; l++) {
            int e = tid + l * 256;          // 0..511
            int r = e >> 2;                 // 0..127
            int c4 = e & 3;                 // 0..3
            float4 v = *(const float4*)(X + (size_t)(bm + r) * 512 + k0 + c4 * 4);
            As[r][c4 * 4 + 0] = v.x;
            As[r][c4 * 4 + 1] = v.y;
            As[r][c4 * 4 + 2] = v.z;
            As[r][c4 * 4 + 3] = v.w;
        }
        // Load W tile 16x64 (256 float4, 1/thread)
        {
            int r = tid >> 4;               // 0..15
            int c4 = tid & 15;              // 0..15
            float4 v = *(const float4*)(W + (size_t)(k0 + r) * 512 + bn + c4 * 4);
            *(float4*)(&Bs[r][c4 * 4]) = v;
        }
        __syncthreads();

        #pragma unroll
        for (int k = 0; k < 16; k++) {
            float a[8];
            #pragma unroll
            for (int i = 0; i < 8; i++) a[i] = As[ty * 8 + i][k];
            float4 b4 = *(const float4*)(&Bs[k][tx * 4]);
            #pragma unroll
            for (int i = 0; i < 8; i++) {
                acc[i][0] += a[i] * b4.x;
                acc[i][1] += a[i] * b4.y;
                acc[i][2] += a[i] * b4.z;
                acc[i][3] += a[i] * b4.w;
            }
        }
        __syncthreads();
    }

    float4 bv = *(const float4*)(bias + bn + tx * 4);
    #pragma unroll
    for (int i = 0; i < 8; i++) {
        float4 o;
        o.x = acc[i][0] + bv.x;
        o.y = acc[i][1] + bv.y;
        o.z = acc[i][2] + bv.z;
        o.w = acc[i][3] + bv.w;
        *(float4*)(C + (size_t)(bm + ty * 8 + i) * 512 + bn + tx * 4) = o;
    }
}

// ---------------------------------------------------------------------------
// Attention: per (b,h). Q-tile=128, K-tile=64, 256 threads.
// Thread (ty,tx) owns score fragment rows ty*8+i (8), cols tx*4+j (4),
// and output fragment rows ty*8+i, dims tx*4+j.
// Q,K stored d-major (transposed) in smem for conflict-free float4 loads.
// Softmax fully distributed (register fragments + shfl row reductions).
// ---------------------------------------------------------------------------
#define SQT 132   // Qt row stride (Qt[64 d][128 qi] + pad4)
#define SKT 68    // Kt row stride (Kt[64 d][64 kj] + pad4)
#define SVS 68    // Vs row stride (Vs[64 kj][64 d] + pad4)
#define SPS 68    // Ps row stride (Ps[128 qi][64 kj] + pad4)
#define ATTN_SMEM_FLOATS (64*SQT + 64*SKT + 64*SVS + 128*SPS)

__global__ __launch_bounds__(256, 2)
void attn_kernel(const float* __restrict__ Qg, const float* __restrict__ Kg,
                 const float* __restrict__ Vg, const float* __restrict__ mask,
                 float* __restrict__ AO) {
    extern __shared__ float sm[];
    float* Qt = sm;                       // [64][SQT]
    float* Kt = Qt + 64 * SQT;            // [64][SKT]
    float* Vs = Kt + 64 * SKT;            // [64][SVS]
    float* Ps = Vs + 64 * SVS;            // [128][SPS] (rows 0..63 double as K staging)

    const int tid = threadIdx.x;
    const int tx = tid & 15;
    const int ty = tid >> 4;
    const int bh = blockIdx.y;
    const int b  = bh >> 3;
    const int h  = bh & 7;
    const int q0 = blockIdx.x * 128;

    const float* Qb = Qg + ((size_t)b * Ss + q0) * 512 + h * 64;
    const float* Kb = Kg + (size_t)b * Ss * 512 + h * 64;
    const float* Vb = Vg + (size_t)b * Ss * 512 + h * 64;
    const float* Mb = mask + (size_t)b * Ss * Ss + (size_t)q0 * Ss;

    // Load Q tile 128x64 and store transposed: Qt[d][qi]
    #pragma unroll
    for (int l = 0; l < 8; l++) {
        int e  = tid + l * 256;            // 0..2047
        int r  = e >> 4;                   // qi 0..127
        int c4 = e & 15;                   // d-chunk
        float4 v = *(const float4*)(Qb + (size_t)r * 512 + c4 * 4);
        Qt[(c4 * 4 + 0) * SQT + r] = v.x;
        Qt[(c4 * 4 + 1) * SQT + r] = v.y;
        Qt[(c4 * 4 + 2) * SQT + r] = v.z;
        Qt[(c4 * 4 + 3) * SQT + r] = v.w;
    }

    float m_i[8], l_i[8], O[8][4];
    #pragma unroll
    for (int i = 0; i < 8; i++) {
        m_i[i] = -1e30f; l_i[i] = 0.f;
        #pragma unroll
        for (int j = 0; j < 4; j++) O[i][j] = 0.f;
    }
    __syncthreads();

    for (int kt = 0; kt < Ss / 64; kt++) {
        const int k0 = kt * 64;

        // 1) K raw -> staging (Ps rows 0..63), V -> Vs (direct layout)
        #pragma unroll
        for (int l = 0; l < 4; l++) {
            int e  = tid + l * 256;        // 0..1023
            int r  = e >> 4;               // 0..63
            int c4 = e & 15;
            float4 kv = *(const float4*)(Kb + (size_t)(k0 + r) * 512 + c4 * 4);
            *(float4*)(Ps + r * SPS + c4 * 4) = kv;
            float4 vv = *(const float4*)(Vb + (size_t)(k0 + r) * 512 + c4 * 4);
            *(float4*)(Vs + r * SVS + c4 * 4) = vv;
        }
        __syncthreads();

        // 2) transpose staging -> Kt[d][kj] (conflict-free LDS.128 + STS)
        #pragma unroll
        for (int l = 0; l < 4; l++) {
            int e  = tid + l * 256;
            int r  = e & 63;               // kj (lane-consecutive)
            int c4 = e >> 6;               // 0..15
            float4 kv = *(const float4*)(Ps + r * SPS + c4 * 4);
            Kt[(c4 * 4 + 0) * SKT + r] = kv.x;
            Kt[(c4 * 4 + 1) * SKT + r] = kv.y;
            Kt[(c4 * 4 + 2) * SKT + r] = kv.z;
            Kt[(c4 * 4 + 3) * SKT + r] = kv.w;
        }
        __syncthreads();

        // 3) scores: P[i][j] = sum_d Qt[d][ty*8+i] * Kt[d][tx*4+j]
        float P[8][4];
        #pragma unroll
        for (int i = 0; i < 8; i++)
            #pragma unroll
            for (int j = 0; j < 4; j++) P[i][j] = 0.f;

        #pragma unroll 4
        for (int d = 0; d < 64; d++) {
            float4 a0 = *(const float4*)(Qt + d * SQT + ty * 8);
            float4 a1 = *(const float4*)(Qt + d * SQT + ty * 8 + 4);
            float4 b4 = *(const float4*)(Kt + d * SKT + tx * 4);
            float a[8] = {a0.x, a0.y, a0.z, a0.w, a1.x, a1.y, a1.z, a1.w};
            #pragma unroll
            for (int i = 0; i < 8; i++) {
                P[i][0] += a[i] * b4.x;
                P[i][1] += a[i] * b4.y;
                P[i][2] += a[i] * b4.z;
                P[i][3] += a[i] * b4.w;
            }
        }

        // 4) mask * scale, threshold, distributed online softmax
        #pragma unroll
        for (int i = 0; i < 8; i++) {
            float4 mk = *(const float4*)(Mb + (size_t)(ty * 8 + i) * Ss + k0 + tx * 4);
            float s0 = P[i][0] * 0.125f * mk.x;
            float s1 = P[i][1] * 0.125f * mk.y;
            float s2 = P[i][2] * 0.125f * mk.z;
            float s3 = P[i][3] * 0.125f * mk.w;
            s0 = (s0 > 0.f) ? s0 : -10000.f;
            s1 = (s1 > 0.f) ? s1 : -10000.f;
            s2 = (s2 > 0.f) ? s2 : -10000.f;
            s3 = (s3 > 0.f) ? s3 : -10000.f;

            float tmax = fmaxf(fmaxf(s0, s1), fmaxf(s2, s3));
            #pragma unroll
            for (int o = 1; o < 16; o <<= 1)
                tmax = fmaxf(tmax, __shfl_xor_sync(0xffffffffu, tmax, o));

            float m_new = fmaxf(m_i[i], tmax);
            float f = __expf(m_i[i] - m_new);
            float e0 = __expf(s0 - m_new);
            float e1 = __expf(s1 - m_new);
            float e2 = __expf(s2 - m_new);
            float e3 = __expf(s3 - m_new);
            float tsum = e0 + e1 + e2 + e3;
            #pragma unroll
            for (int o = 1; o < 16; o <<= 1)
                tsum += __shfl_xor_sync(0xffffffffu, tsum, o);

            l_i[i] = l_i[i] * f + tsum;
            m_i[i] = m_new;
            O[i][0] *= f; O[i][1] *= f; O[i][2] *= f; O[i][3] *= f;

            P[i][0] = e0; P[i][1] = e1; P[i][2] = e2; P[i][3] = e3;
        }

        // write P fragments to smem for cross-thread AV
        #pragma unroll
        for (int i = 0; i < 8; i++) {
            float4 pv = {P[i][0], P[i][1], P[i][2], P[i][3]};
            *(float4*)(Ps + (ty * 8 + i) * SPS + tx * 4) = pv;
        }
        __syncthreads();

        // 5) AV: O[i][j] += sum_kj Ps[ty*8+i][kj] * Vs[kj][tx*4+j]
        #pragma unroll 2
        for (int kj4 = 0; kj4 < 16; kj4++) {
            float4 p4[8];
            #pragma unroll
            for (int i = 0; i < 8; i++)
                p4[i] = *(const float4*)(Ps + (ty * 8 + i) * SPS + kj4 * 4);
            #pragma unroll
            for (int jj = 0; jj < 4; jj++) {
                float4 v4 = *(const float4*)(Vs + (kj4 * 4 + jj) * SVS + tx * 4);
                #pragma unroll
                for (int i = 0; i < 8; i++) {
                    float p = (jj == 0) ? p4[i].x : (jj == 1) ? p4[i].y
                            : (jj == 2) ? p4[i].z : p4[i].w;
                    O[i][0] += p * v4.x;
                    O[i][1] += p * v4.y;
                    O[i][2] += p * v4.z;
                    O[i][3] += p * v4.w;
                }
            }
        }
        __syncthreads();
    }

    // final normalize + write
    #pragma unroll
    for (int i = 0; i < 8; i++) {
        float inv = 1.f / l_i[i];
        float4 o;
        o.x = O[i][0] * inv;
        o.y = O[i][1] * inv;
        o.z = O[i][2] * inv;
        o.w = O[i][3] * inv;
        *(float4*)(AO + ((size_t)b * Ss + q0 + ty * 8 + i) * 512 + h * 64 + tx * 4) = o;
    }
}

// ---------------------------------------------------------------------------
// Residual + LayerNorm
// ---------------------------------------------------------------------------
__global__ __launch_bounds__(512)
void ln_kernel(const float* __restrict__ q, const float* __restrict__ gamma,
               const float* __restrict__ beta, float* __restrict__ out) {
    __shared__ float rs[16], rs2[16];
    const int r = blockIdx.x;
    const int j = threadIdx.x;

    const float v = q[(size_t)r * 512 + j] + g_P[(size_t)r * 512 + j];

    float s = v, s2 = v * v;
    #pragma unroll
    for (int o = 16; o > 0; o >>= 1) {
        s  += __shfl_xor_sync(0xffffffffu, s,  o);
        s2 += __shfl_xor_sync(0xffffffffu, s2, o);
    }
    const int w = j >> 5, ln = j & 31;
    if (ln == 0) { rs[w] = s; rs2[w] = s2; }
    __syncthreads();
    if (w == 0) {
        s  = (ln < 16) ? rs[ln]  : 0.f;
        s2 = (ln < 16) ? rs2[ln] : 0.f;
        #pragma unroll
        for (int o = 8; o > 0; o >>= 1) {
            s  += __shfl_xor_sync(0xffffffffu, s,  o);
            s2 += __shfl_xor_sync(0xffffffffu, s2, o);
        }
        if (ln == 0) { rs[0] = s; rs2[0] = s2; }
    }
    __syncthreads();

    const float mu  = rs[0] * (1.f / 512.f);
    const float var = rs2[0] * (1.f / 512.f) - mu * mu;
    const float inv = rsqrtf(var + 1e-5f);
    out[(size_t)r * 512 + j] = (v - mu) * inv * gamma[j] + beta[j];
}

// ---------------------------------------------------------------------------
extern "C" void kernel_launch(void* const* d_in, const int* in_sizes, int n_in,
                              void* d_out, int out_size) {
    const float* q     = (const float*)d_in[0];
    const float* k     = (const float*)d_in[1];
    const float* v     = (const float*)d_in[2];
    const float* mask  = (const float*)d_in[3];
    const float* Wq    = (const float*)d_in[4];
    const float* bq    = (const float*)d_in[5];
    const float* Wk    = (const float*)d_in[6];
    const float* bk    = (const float*)d_in[7];
    const float* Wv    = (const float*)d_in[8];
    const float* bv    = (const float*)d_in[9];
    const float* Wo    = (const float*)d_in[10];
    const float* bo    = (const float*)d_in[11];
    const float* gamma = (const float*)d_in[12];
    const float* beta  = (const float*)d_in[13];
    float* out = (float*)d_out;

    float *gQ, *gK, *gV, *gAO, *gP;
    cudaGetSymbolAddress((void**)&gQ,  g_Q);
    cudaGetSymbolAddress((void**)&gK,  g_K);
    cudaGetSymbolAddress((void**)&gV,  g_V);
    cudaGetSymbolAddress((void**)&gAO, g_AO);
    cudaGetSymbolAddress((void**)&gP,  g_P);

    const int attn_smem = ATTN_SMEM_FLOATS * sizeof(float);
    cudaFuncSetAttribute(attn_kernel, cudaFuncAttributeMaxDynamicSharedMemorySize,
                         attn_smem);

    dim3 gg(MROWS / 128, 512 / 64);
    gemm_bias_kernel<<<gg, 256>>>(q, Wq, bq, gQ);
    gemm_bias_kernel<<<gg, 256>>>(k, Wk, bk, gK);
    gemm_bias_kernel<<<gg, 256>>>(v, Wv, bv, gV);

    attn_kernel<<<dim3(Ss / 128, Bb * Hh), 256, attn_smem>>>(gQ, gK, gV, mask, gAO);

    gemm_bias_kernel<<<gg, 256>>>(gAO, Wo, bo, gP);

    ln_kernel<<<MROWS, 512>>>(q, gamma, beta, out);
}

// round 4
// speedup vs baseline: 3.7224x; 1.3686x over previous
#include <cuda_runtime.h>
#include <cstddef>
#include <cstdint>

#define Bb   4
#define Ss   2048
#define DIN  512
#define Hh   8
#define DM   512
#define MROWS (Bb*Ss)          // 8192

// Scratch (device globals: allocation-free rule)
__device__ float g_Q [MROWS*DM];
__device__ float g_K [MROWS*DM];
__device__ float g_V [MROWS*DM];
__device__ float g_AO[MROWS*DM];
__device__ float g_P [MROWS*DIN];

// ===========================================================================
// helpers
// ===========================================================================
__device__ __forceinline__ uint32_t f2tf32(float f) {
    uint32_t r;
    asm("cvt.rna.tf32.f32 %0, %1;" : "=r"(r) : "f"(f));
    return r;
}

// D += A * B  (m16n8k8, tf32 inputs, fp32 accum). row.col.
__device__ __forceinline__ void mma_tf32(float* d, const uint32_t* a,
                                         uint32_t b0, uint32_t b1) {
    asm volatile(
        "mma.sync.aligned.m16n8k8.row.col.f32.tf32.tf32.f32 "
        "{%0,%1,%2,%3}, {%4,%5,%6,%7}, {%8,%9}, {%0,%1,%2,%3};"
        : "+f"(d[0]), "+f"(d[1]), "+f"(d[2]), "+f"(d[3])
        : "r"(a[0]), "r"(a[1]), "r"(a[2]), "r"(a[3]), "r"(b0), "r"(b1));
}

// ===========================================================================
// GEMM: C[M,512] = X[M,512] @ W[512,512] + bias  (scalar, proven R2 version)
// ===========================================================================
__global__ __launch_bounds__(256)
void gemm_bias_kernel(const float* __restrict__ X, const float* __restrict__ W,
                      const float* __restrict__ bias, float* __restrict__ C) {
    __shared__ float As[128][17];
    __shared__ float Bs[16][68];

    const int tid = threadIdx.x;
    const int tx = tid & 15;
    const int ty = tid >> 4;
    const int bm = blockIdx.x * 128;
    const int bn = blockIdx.y * 64;

    float acc[8][4];
    #pragma unroll
    for (int i = 0; i < 8; i++)
        #pragma unroll
        for (int j = 0; j < 4; j++) acc[i][j] = 0.f;

    for (int k0 = 0; k0 < 512; k0 += 16) {
        #pragma unroll
        for (int l = 0; l < 2; l++) {
            int e = tid + l * 256;
            int r = e >> 2, c4 = e & 3;
            float4 v = *(const float4*)(X + (size_t)(bm + r) * 512 + k0 + c4 * 4);
            As[r][c4 * 4 + 0] = v.x; As[r][c4 * 4 + 1] = v.y;
            As[r][c4 * 4 + 2] = v.z; As[r][c4 * 4 + 3] = v.w;
        }
        {
            int r = tid >> 4, c4 = tid & 15;
            float4 v = *(const float4*)(W + (size_t)(k0 + r) * 512 + bn + c4 * 4);
            *(float4*)(&Bs[r][c4 * 4]) = v;
        }
        __syncthreads();
        #pragma unroll
        for (int k = 0; k < 16; k++) {
            float a[8];
            #pragma unroll
            for (int i = 0; i < 8; i++) a[i] = As[ty * 8 + i][k];
            float4 b4 = *(const float4*)(&Bs[k][tx * 4]);
            #pragma unroll
            for (int i = 0; i < 8; i++) {
                acc[i][0] += a[i] * b4.x; acc[i][1] += a[i] * b4.y;
                acc[i][2] += a[i] * b4.z; acc[i][3] += a[i] * b4.w;
            }
        }
        __syncthreads();
    }

    float4 bv = *(const float4*)(bias + bn + tx * 4);
    #pragma unroll
    for (int i = 0; i < 8; i++) {
        float4 o;
        o.x = acc[i][0] + bv.x; o.y = acc[i][1] + bv.y;
        o.z = acc[i][2] + bv.z; o.w = acc[i][3] + bv.w;
        *(float4*)(C + (size_t)(bm + ty * 8 + i) * 512 + bn + tx * 4) = o;
    }
}

// ===========================================================================
// mma.sync tf32 flash attention. 1 CTA = (b,h), 128 q-rows, 8 warps (256 thr).
// Warp w owns q-rows [w*16, w*16+16). K/V double-buffered in smem (stride 72).
// ===========================================================================
#define KSTR 72
#define SM_K0 0
#define SM_K1 (64*KSTR)
#define SM_V0 (2*64*KSTR)
#define SM_V1 (SM_V0 + 64*KSTR)
#define SM_P  (SM_V0 + 2*64*KSTR)
#define ATTN_SMEM_FLOATS (SM_P + 128*KSTR)
#define ATTN_SMEM_BYTES  (ATTN_SMEM_FLOATS * 4)   // 110592

__global__ __launch_bounds__(256, 1)
void attn_mma_kernel(const float* __restrict__ Qg, const float* __restrict__ Kg,
                     const float* __restrict__ Vg, const float* __restrict__ mask,
                     float* __restrict__ AO) {
    extern __shared__ float sm[];
    const int tid  = threadIdx.x;
    const int lane = tid & 31;
    const int wid  = tid >> 5;
    const int gid  = lane >> 2;   // 0..7 (row within half-fragment)
    const int tig  = lane & 3;    // 0..3

    const int bh = blockIdx.y;
    const int b  = bh >> 3;
    const int h  = bh & 7;
    const int q0 = blockIdx.x * 128;

    const float* Kb = Kg + (size_t)b * Ss * 512 + h * 64;
    const float* Vb = Vg + (size_t)b * Ss * 512 + h * 64;

    // ---- persistent Q A-fragments (pre-scaled 1/8, tf32) ----
    const int qrow = q0 + wid * 16 + gid;
    const float* Qp = Qg + ((size_t)b * Ss + qrow) * 512 + h * 64;
    uint32_t Qa[8][4];
    #pragma unroll
    for (int ch = 0; ch < 8; ch++) {
        Qa[ch][0] = f2tf32(Qp[ch * 8 + tig] * 0.125f);
        Qa[ch][1] = f2tf32(Qp[8 * 512 + ch * 8 + tig] * 0.125f);
        Qa[ch][2] = f2tf32(Qp[ch * 8 + tig + 4] * 0.125f);
        Qa[ch][3] = f2tf32(Qp[8 * 512 + ch * 8 + tig + 4] * 0.125f);
    }

    // ---- K/V tile loader (tf32-converted, stride-72 rows) ----
    auto load_kv = [&](int k0, int sel) {
        float* Ks = sm + (sel ? SM_K1 : SM_K0);
        float* Vs = sm + (sel ? SM_V1 : SM_V0);
        #pragma unroll
        for (int l = 0; l < 4; l++) {
            int e = tid + l * 256;       // 0..1023
            int r = e >> 4, c4 = e & 15; // 64 rows x 16 float4
            float4 kv = *(const float4*)(Kb + (size_t)(k0 + r) * 512 + c4 * 4);
            uint4 tk = { f2tf32(kv.x), f2tf32(kv.y), f2tf32(kv.z), f2tf32(kv.w) };
            *(uint4*)(Ks + r * KSTR + c4 * 4) = tk;
            float4 vv = *(const float4*)(Vb + (size_t)(k0 + r) * 512 + c4 * 4);
            uint4 tv = { f2tf32(vv.x), f2tf32(vv.y), f2tf32(vv.z), f2tf32(vv.w) };
            *(uint4*)(Vs + r * KSTR + c4 * 4) = tv;
        }
    };

    load_kv(0, 0);

    const float* Mrow0 = mask + (size_t)b * Ss * Ss + (size_t)qrow * Ss;
    const float* Mrow1 = Mrow0 + (size_t)8 * Ss;
    float* Pw = sm + SM_P + wid * 16 * KSTR;

    float m0 = -1e30f, m1 = -1e30f, l0 = 0.f, l1 = 0.f;
    float O[8][4];
    #pragma unroll
    for (int j = 0; j < 8; j++)
        #pragma unroll
        for (int c = 0; c < 4; c++) O[j][c] = 0.f;

    __syncthreads();

    for (int kt = 0; kt < 32; kt++) {
        const int sel = kt & 1;
        const int k0  = kt * 64;
        const float* Ks = sm + (sel ? SM_K1 : SM_K0);
        const float* Vs = sm + (sel ? SM_V1 : SM_V0);

        // ---- S = Q K^T (scaled): 8 key-frags x 8 d-chunks ----
        float S[8][4];
        #pragma unroll
        for (int kf = 0; kf < 8; kf++) {
            S[kf][0] = 0.f; S[kf][1] = 0.f; S[kf][2] = 0.f; S[kf][3] = 0.f;
            #pragma unroll
            for (int ch = 0; ch < 8; ch++) {
                const float* kp = Ks + (kf * 8 + gid) * KSTR + ch * 8 + tig;
                uint32_t b0 = __float_as_uint(kp[0]);
                uint32_t b1 = __float_as_uint(kp[4]);
                mma_tf32(S[kf], Qa[ch], b0, b1);
            }
        }

        // ---- mask * s, threshold, row max ----
        float mx0 = m0, mx1 = m1;
        #pragma unroll
        for (int kf = 0; kf < 8; kf++) {
            float2 mk0 = *(const float2*)(Mrow0 + k0 + kf * 8 + 2 * tig);
            float2 mk1 = *(const float2*)(Mrow1 + k0 + kf * 8 + 2 * tig);
            float s0 = S[kf][0] * mk0.x;
            float s1 = S[kf][1] * mk0.y;
            float s2 = S[kf][2] * mk1.x;
            float s3 = S[kf][3] * mk1.y;
            s0 = (s0 > 0.f) ? s0 : -10000.f;
            s1 = (s1 > 0.f) ? s1 : -10000.f;
            s2 = (s2 > 0.f) ? s2 : -10000.f;
            s3 = (s3 > 0.f) ? s3 : -10000.f;
            S[kf][0] = s0; S[kf][1] = s1; S[kf][2] = s2; S[kf][3] = s3;
            mx0 = fmaxf(mx0, fmaxf(s0, s1));
            mx1 = fmaxf(mx1, fmaxf(s2, s3));
        }
        mx0 = fmaxf(mx0, __shfl_xor_sync(0xffffffffu, mx0, 1));
        mx0 = fmaxf(mx0, __shfl_xor_sync(0xffffffffu, mx0, 2));
        mx1 = fmaxf(mx1, __shfl_xor_sync(0xffffffffu, mx1, 1));
        mx1 = fmaxf(mx1, __shfl_xor_sync(0xffffffffu, mx1, 2));

        // ---- exp, write P (tf32) to warp-private smem ----
        float f0 = __expf(m0 - mx0);
        float f1 = __expf(m1 - mx1);
        float sum0 = 0.f, sum1 = 0.f;
        #pragma unroll
        for (int kf = 0; kf < 8; kf++) {
            float p0 = __expf(S[kf][0] - mx0);
            float p1 = __expf(S[kf][1] - mx0);
            float p2 = __expf(S[kf][2] - mx1);
            float p3 = __expf(S[kf][3] - mx1);
            sum0 += p0 + p1;
            sum1 += p2 + p3;
            float2 w0 = { __uint_as_float(f2tf32(p0)), __uint_as_float(f2tf32(p1)) };
            float2 w1 = { __uint_as_float(f2tf32(p2)), __uint_as_float(f2tf32(p3)) };
            *(float2*)(Pw + gid * KSTR + kf * 8 + 2 * tig) = w0;
            *(float2*)(Pw + (gid + 8) * KSTR + kf * 8 + 2 * tig) = w1;
        }
        sum0 += __shfl_xor_sync(0xffffffffu, sum0, 1);
        sum0 += __shfl_xor_sync(0xffffffffu, sum0, 2);
        sum1 += __shfl_xor_sync(0xffffffffu, sum1, 1);
        sum1 += __shfl_xor_sync(0xffffffffu, sum1, 2);

        l0 = l0 * f0 + sum0;  m0 = mx0;
        l1 = l1 * f1 + sum1;  m1 = mx1;

        #pragma unroll
        for (int j = 0; j < 8; j++) {
            O[j][0] *= f0; O[j][1] *= f0;
            O[j][2] *= f1; O[j][3] *= f1;
        }
        __syncwarp();

        // ---- O += P @ V : 8 key-chunks (k) x 8 d-frags (n) ----
        #pragma unroll
        for (int kc = 0; kc < 8; kc++) {
            uint32_t A[4];
            A[0] = __float_as_uint(Pw[gid * KSTR + kc * 8 + tig]);
            A[1] = __float_as_uint(Pw[(gid + 8) * KSTR + kc * 8 + tig]);
            A[2] = __float_as_uint(Pw[gid * KSTR + kc * 8 + tig + 4]);
            A[3] = __float_as_uint(Pw[(gid + 8) * KSTR + kc * 8 + tig + 4]);
            #pragma unroll
            for (int df = 0; df < 8; df++) {
                const float* vp = Vs + (kc * 8 + tig) * KSTR + df * 8 + gid;
                uint32_t b0 = __float_as_uint(vp[0]);
                uint32_t b1 = __float_as_uint(vp[4 * KSTR]);
                mma_tf32(O[df], A, b0, b1);
            }
        }

        // ---- prefetch next tile into the other buffer ----
        if (kt < 31) load_kv(k0 + 64, sel ^ 1);
        __syncthreads();
    }

    // ---- epilogue: normalize + write ----
    const float inv0 = 1.f / l0;
    const float inv1 = 1.f / l1;
    float* Op0 = AO + ((size_t)b * Ss + qrow) * 512 + h * 64;
    float* Op1 = Op0 + (size_t)8 * 512;
    #pragma unroll
    for (int df = 0; df < 8; df++) {
        float2 o0 = { O[df][0] * inv0, O[df][1] * inv0 };
        float2 o1 = { O[df][2] * inv1, O[df][3] * inv1 };
        *(float2*)(Op0 + df * 8 + 2 * tig) = o0;
        *(float2*)(Op1 + df * 8 + 2 * tig) = o1;
    }
}

// ===========================================================================
// Residual + LayerNorm
// ===========================================================================
__global__ __launch_bounds__(512)
void ln_kernel(const float* __restrict__ q, const float* __restrict__ gamma,
               const float* __restrict__ beta, float* __restrict__ out) {
    __shared__ float rs[16], rs2[16];
    const int r = blockIdx.x;
    const int j = threadIdx.x;

    const float v = q[(size_t)r * 512 + j] + g_P[(size_t)r * 512 + j];

    float s = v, s2 = v * v;
    #pragma unroll
    for (int o = 16; o > 0; o >>= 1) {
        s  += __shfl_xor_sync(0xffffffffu, s,  o);
        s2 += __shfl_xor_sync(0xffffffffu, s2, o);
    }
    const int w = j >> 5, ln = j & 31;
    if (ln == 0) { rs[w] = s; rs2[w] = s2; }
    __syncthreads();
    if (w == 0) {
        s  = (ln < 16) ? rs[ln]  : 0.f;
        s2 = (ln < 16) ? rs2[ln] : 0.f;
        #pragma unroll
        for (int o = 8; o > 0; o >>= 1) {
            s  += __shfl_xor_sync(0xffffffffu, s,  o);
            s2 += __shfl_xor_sync(0xffffffffu, s2, o);
        }
        if (ln == 0) { rs[0] = s; rs2[0] = s2; }
    }
    __syncthreads();

    const float mu  = rs[0] * (1.f / 512.f);
    const float var = rs2[0] * (1.f / 512.f) - mu * mu;
    const float inv = rsqrtf(var + 1e-5f);
    out[(size_t)r * 512 + j] = (v - mu) * inv * gamma[j] + beta[j];
}

// ===========================================================================
extern "C" void kernel_launch(void* const* d_in, const int* in_sizes, int n_in,
                              void* d_out, int out_size) {
    const float* q     = (const float*)d_in[0];
    const float* k     = (const float*)d_in[1];
    const float* v     = (const float*)d_in[2];
    const float* mask  = (const float*)d_in[3];
    const float* Wq    = (const float*)d_in[4];
    const float* bq    = (const float*)d_in[5];
    const float* Wk    = (const float*)d_in[6];
    const float* bk    = (const float*)d_in[7];
    const float* Wv    = (const float*)d_in[8];
    const float* bv    = (const float*)d_in[9];
    const float* Wo    = (const float*)d_in[10];
    const float* bo    = (const float*)d_in[11];
    const float* gamma = (const float*)d_in[12];
    const float* beta  = (const float*)d_in[13];
    float* out = (float*)d_out;

    float *gQ, *gK, *gV, *gAO, *gP;
    cudaGetSymbolAddress((void**)&gQ,  g_Q);
    cudaGetSymbolAddress((void**)&gK,  g_K);
    cudaGetSymbolAddress((void**)&gV,  g_V);
    cudaGetSymbolAddress((void**)&gAO, g_AO);
    cudaGetSymbolAddress((void**)&gP,  g_P);

    cudaFuncSetAttribute(attn_mma_kernel,
                         cudaFuncAttributeMaxDynamicSharedMemorySize,
                         ATTN_SMEM_BYTES);

    dim3 gg(MROWS / 128, 512 / 64);
    gemm_bias_kernel<<<gg, 256>>>(q, Wq, bq, gQ);
    gemm_bias_kernel<<<gg, 256>>>(k, Wk, bk, gK);
    gemm_bias_kernel<<<gg, 256>>>(v, Wv, bv, gV);

    attn_mma_kernel<<<dim3(Ss / 128, Bb * Hh), 256, ATTN_SMEM_BYTES>>>(gQ, gK, gV, mask, gAO);

    gemm_bias_kernel<<<gg, 256>>>(gAO, Wo, bo, gP);

    ln_kernel<<<MROWS, 512>>>(q, gamma, beta, out);
}

// round 5
// speedup vs baseline: 5.4229x; 1.4568x over previous
#include <cuda_runtime.h>
#include <cstddef>
#include <cstdint>

#define Bb   4
#define Ss   2048
#define DIN  512
#define Hh   8
#define DM   512
#define MROWS (Bb*Ss)          // 8192

// Scratch (device globals: allocation-free rule)
__device__ float g_Q [MROWS*DM];
__device__ float g_K [MROWS*DM];
__device__ float g_V [MROWS*DM];
__device__ float g_AO[MROWS*DM];
__device__ float g_P [MROWS*DIN];

// ===========================================================================
// helpers
// ===========================================================================
__device__ __forceinline__ uint32_t f2tf32(float f) {
    uint32_t r;
    asm("cvt.rna.tf32.f32 %0, %1;" : "=r"(r) : "f"(f));
    return r;
}

// D += A * B  (m16n8k8, tf32 inputs, fp32 accum). row.col.
__device__ __forceinline__ void mma_tf32(float* d, const uint32_t* a,
                                         uint32_t b0, uint32_t b1) {
    asm volatile(
        "mma.sync.aligned.m16n8k8.row.col.f32.tf32.tf32.f32 "
        "{%0,%1,%2,%3}, {%4,%5,%6,%7}, {%8,%9}, {%0,%1,%2,%3};"
        : "+f"(d[0]), "+f"(d[1]), "+f"(d[2]), "+f"(d[3])
        : "r"(a[0]), "r"(a[1]), "r"(a[2]), "r"(a[3]), "r"(b0), "r"(b1));
}

// ===========================================================================
// Tensor-core GEMM: C[M,512] = X[M,512] @ W[512,512] + bias   (tf32 mma.sync)
// BM=128, BN=128, BK=32. 256 threads = 8 warps (2 m x 4 n), 64x32 per warp.
// Xs[m][k] stride 36; Ws[k][n] stride 136 (both give conflict-free frag LDS).
// ===========================================================================
#define XS_STR 36
#define WS_STR 136

__global__ __launch_bounds__(256)
void gemm_tc_kernel(const float* __restrict__ X, const float* __restrict__ W,
                    const float* __restrict__ bias, float* __restrict__ C) {
    __shared__ float Xs[128 * XS_STR];
    __shared__ float Ws[32 * WS_STR];

    const int tid  = threadIdx.x;
    const int lane = tid & 31;
    const int wid  = tid >> 5;
    const int gid  = lane >> 2;
    const int tig  = lane & 3;

    const int warp_m = wid >> 2;          // 0..1
    const int warp_n = wid & 3;           // 0..3
    const int m_base = warp_m * 64;
    const int n_base = warp_n * 32;

    const int bm = blockIdx.x * 128;
    const int bn = blockIdx.y * 128;

    float acc[4][4][4];
    #pragma unroll
    for (int mf = 0; mf < 4; mf++)
        #pragma unroll
        for (int nf = 0; nf < 4; nf++)
            #pragma unroll
            for (int c = 0; c < 4; c++) acc[mf][nf][c] = 0.f;

    for (int k0 = 0; k0 < 512; k0 += 32) {
        // X tile 128x32 -> Xs[m][k] (tf32)
        #pragma unroll
        for (int l = 0; l < 4; l++) {
            int e = tid + l * 256;          // 0..1023
            int r = e >> 3, c4 = e & 7;
            float4 v = *(const float4*)(X + (size_t)(bm + r) * 512 + k0 + c4 * 4);
            uint4 t = { f2tf32(v.x), f2tf32(v.y), f2tf32(v.z), f2tf32(v.w) };
            *(uint4*)(Xs + r * XS_STR + c4 * 4) = t;
        }
        // W tile 32x128 -> Ws[k][n] (tf32)
        #pragma unroll
        for (int l = 0; l < 4; l++) {
            int e = tid + l * 256;
            int r = e >> 5, c4 = e & 31;
            float4 v = *(const float4*)(W + (size_t)(k0 + r) * 512 + bn + c4 * 4);
            uint4 t = { f2tf32(v.x), f2tf32(v.y), f2tf32(v.z), f2tf32(v.w) };
            *(uint4*)(Ws + r * WS_STR + c4 * 4) = t;
        }
        __syncthreads();

        #pragma unroll
        for (int ks = 0; ks < 4; ks++) {
            const int kk = ks * 8;
            uint32_t A[4][4];
            #pragma unroll
            for (int mf = 0; mf < 4; mf++) {
                const float* ap = Xs + (m_base + mf * 16 + gid) * XS_STR + kk + tig;
                A[mf][0] = __float_as_uint(ap[0]);
                A[mf][1] = __float_as_uint(ap[8 * XS_STR]);
                A[mf][2] = __float_as_uint(ap[4]);
                A[mf][3] = __float_as_uint(ap[8 * XS_STR + 4]);
            }
            #pragma unroll
            for (int nf = 0; nf < 4; nf++) {
                const float* bp = Ws + (kk + tig) * WS_STR + n_base + nf * 8 + gid;
                uint32_t b0 = __float_as_uint(bp[0]);
                uint32_t b1 = __float_as_uint(bp[4 * WS_STR]);
                #pragma unroll
                for (int mf = 0; mf < 4; mf++)
                    mma_tf32(acc[mf][nf], A[mf], b0, b1);
            }
        }
        __syncthreads();
    }

    // epilogue: bias + store (C-frag layout: c0,c1 row gid; c2,c3 row gid+8)
    #pragma unroll
    for (int nf = 0; nf < 4; nf++) {
        const int col = bn + n_base + nf * 8 + 2 * tig;
        float2 b2 = *(const float2*)(bias + col);
        #pragma unroll
        for (int mf = 0; mf < 4; mf++) {
            const int row0 = bm + m_base + mf * 16 + gid;
            float2 o0 = { acc[mf][nf][0] + b2.x, acc[mf][nf][1] + b2.y };
            float2 o1 = { acc[mf][nf][2] + b2.x, acc[mf][nf][3] + b2.y };
            *(float2*)(C + (size_t)row0 * 512 + col) = o0;
            *(float2*)(C + (size_t)(row0 + 8) * 512 + col) = o1;
        }
    }
}

// ===========================================================================
// mma.sync tf32 flash attention (proven R4 version, unchanged).
// ===========================================================================
#define KSTR 72
#define SM_K0 0
#define SM_K1 (64*KSTR)
#define SM_V0 (2*64*KSTR)
#define SM_V1 (SM_V0 + 64*KSTR)
#define SM_P  (SM_V0 + 2*64*KSTR)
#define ATTN_SMEM_FLOATS (SM_P + 128*KSTR)
#define ATTN_SMEM_BYTES  (ATTN_SMEM_FLOATS * 4)   // 110592

__global__ __launch_bounds__(256, 1)
void attn_mma_kernel(const float* __restrict__ Qg, const float* __restrict__ Kg,
                     const float* __restrict__ Vg, const float* __restrict__ mask,
                     float* __restrict__ AO) {
    extern __shared__ float sm[];
    const int tid  = threadIdx.x;
    const int lane = tid & 31;
    const int wid  = tid >> 5;
    const int gid  = lane >> 2;
    const int tig  = lane & 3;

    const int bh = blockIdx.y;
    const int b  = bh >> 3;
    const int h  = bh & 7;
    const int q0 = blockIdx.x * 128;

    const float* Kb = Kg + (size_t)b * Ss * 512 + h * 64;
    const float* Vb = Vg + (size_t)b * Ss * 512 + h * 64;

    const int qrow = q0 + wid * 16 + gid;
    const float* Qp = Qg + ((size_t)b * Ss + qrow) * 512 + h * 64;
    uint32_t Qa[8][4];
    #pragma unroll
    for (int ch = 0; ch < 8; ch++) {
        Qa[ch][0] = f2tf32(Qp[ch * 8 + tig] * 0.125f);
        Qa[ch][1] = f2tf32(Qp[8 * 512 + ch * 8 + tig] * 0.125f);
        Qa[ch][2] = f2tf32(Qp[ch * 8 + tig + 4] * 0.125f);
        Qa[ch][3] = f2tf32(Qp[8 * 512 + ch * 8 + tig + 4] * 0.125f);
    }

    auto load_kv = [&](int k0, int sel) {
        float* Ks = sm + (sel ? SM_K1 : SM_K0);
        float* Vs = sm + (sel ? SM_V1 : SM_V0);
        #pragma unroll
        for (int l = 0; l < 4; l++) {
            int e = tid + l * 256;
            int r = e >> 4, c4 = e & 15;
            float4 kv = *(const float4*)(Kb + (size_t)(k0 + r) * 512 + c4 * 4);
            uint4 tk = { f2tf32(kv.x), f2tf32(kv.y), f2tf32(kv.z), f2tf32(kv.w) };
            *(uint4*)(Ks + r * KSTR + c4 * 4) = tk;
            float4 vv = *(const float4*)(Vb + (size_t)(k0 + r) * 512 + c4 * 4);
            uint4 tv = { f2tf32(vv.x), f2tf32(vv.y), f2tf32(vv.z), f2tf32(vv.w) };
            *(uint4*)(Vs + r * KSTR + c4 * 4) = tv;
        }
    };

    load_kv(0, 0);

    const float* Mrow0 = mask + (size_t)b * Ss * Ss + (size_t)qrow * Ss;
    const float* Mrow1 = Mrow0 + (size_t)8 * Ss;
    float* Pw = sm + SM_P + wid * 16 * KSTR;

    float m0 = -1e30f, m1 = -1e30f, l0 = 0.f, l1 = 0.f;
    float O[8][4];
    #pragma unroll
    for (int j = 0; j < 8; j++)
        #pragma unroll
        for (int c = 0; c < 4; c++) O[j][c] = 0.f;

    __syncthreads();

    for (int kt = 0; kt < 32; kt++) {
        const int sel = kt & 1;
        const int k0  = kt * 64;
        const float* Ks = sm + (sel ? SM_K1 : SM_K0);
        const float* Vs = sm + (sel ? SM_V1 : SM_V0);

        float S[8][4];
        #pragma unroll
        for (int kf = 0; kf < 8; kf++) {
            S[kf][0] = 0.f; S[kf][1] = 0.f; S[kf][2] = 0.f; S[kf][3] = 0.f;
            #pragma unroll
            for (int ch = 0; ch < 8; ch++) {
                const float* kp = Ks + (kf * 8 + gid) * KSTR + ch * 8 + tig;
                uint32_t b0 = __float_as_uint(kp[0]);
                uint32_t b1 = __float_as_uint(kp[4]);
                mma_tf32(S[kf], Qa[ch], b0, b1);
            }
        }

        float mx0 = m0, mx1 = m1;
        #pragma unroll
        for (int kf = 0; kf < 8; kf++) {
            float2 mk0 = *(const float2*)(Mrow0 + k0 + kf * 8 + 2 * tig);
            float2 mk1 = *(const float2*)(Mrow1 + k0 + kf * 8 + 2 * tig);
            float s0 = S[kf][0] * mk0.x;
            float s1 = S[kf][1] * mk0.y;
            float s2 = S[kf][2] * mk1.x;
            float s3 = S[kf][3] * mk1.y;
            s0 = (s0 > 0.f) ? s0 : -10000.f;
            s1 = (s1 > 0.f) ? s1 : -10000.f;
            s2 = (s2 > 0.f) ? s2 : -10000.f;
            s3 = (s3 > 0.f) ? s3 : -10000.f;
            S[kf][0] = s0; S[kf][1] = s1; S[kf][2] = s2; S[kf][3] = s3;
            mx0 = fmaxf(mx0, fmaxf(s0, s1));
            mx1 = fmaxf(mx1, fmaxf(s2, s3));
        }
        mx0 = fmaxf(mx0, __shfl_xor_sync(0xffffffffu, mx0, 1));
        mx0 = fmaxf(mx0, __shfl_xor_sync(0xffffffffu, mx0, 2));
        mx1 = fmaxf(mx1, __shfl_xor_sync(0xffffffffu, mx1, 1));
        mx1 = fmaxf(mx1, __shfl_xor_sync(0xffffffffu, mx1, 2));

        float f0 = __expf(m0 - mx0);
        float f1 = __expf(m1 - mx1);
        float sum0 = 0.f, sum1 = 0.f;
        #pragma unroll
        for (int kf = 0; kf < 8; kf++) {
            float p0 = __expf(S[kf][0] - mx0);
            float p1 = __expf(S[kf][1] - mx0);
            float p2 = __expf(S[kf][2] - mx1);
            float p3 = __expf(S[kf][3] - mx1);
            sum0 += p0 + p1;
            sum1 += p2 + p3;
            float2 w0 = { __uint_as_float(f2tf32(p0)), __uint_as_float(f2tf32(p1)) };
            float2 w1 = { __uint_as_float(f2tf32(p2)), __uint_as_float(f2tf32(p3)) };
            *(float2*)(Pw + gid * KSTR + kf * 8 + 2 * tig) = w0;
            *(float2*)(Pw + (gid + 8) * KSTR + kf * 8 + 2 * tig) = w1;
        }
        sum0 += __shfl_xor_sync(0xffffffffu, sum0, 1);
        sum0 += __shfl_xor_sync(0xffffffffu, sum0, 2);
        sum1 += __shfl_xor_sync(0xffffffffu, sum1, 1);
        sum1 += __shfl_xor_sync(0xffffffffu, sum1, 2);

        l0 = l0 * f0 + sum0;  m0 = mx0;
        l1 = l1 * f1 + sum1;  m1 = mx1;

        #pragma unroll
        for (int j = 0; j < 8; j++) {
            O[j][0] *= f0; O[j][1] *= f0;
            O[j][2] *= f1; O[j][3] *= f1;
        }
        __syncwarp();

        #pragma unroll
        for (int kc = 0; kc < 8; kc++) {
            uint32_t A[4];
            A[0] = __float_as_uint(Pw[gid * KSTR + kc * 8 + tig]);
            A[1] = __float_as_uint(Pw[(gid + 8) * KSTR + kc * 8 + tig]);
            A[2] = __float_as_uint(Pw[gid * KSTR + kc * 8 + tig + 4]);
            A[3] = __float_as_uint(Pw[(gid + 8) * KSTR + kc * 8 + tig + 4]);
            #pragma unroll
            for (int df = 0; df < 8; df++) {
                const float* vp = Vs + (kc * 8 + tig) * KSTR + df * 8 + gid;
                uint32_t b0 = __float_as_uint(vp[0]);
                uint32_t b1 = __float_as_uint(vp[4 * KSTR]);
                mma_tf32(O[df], A, b0, b1);
            }
        }

        if (kt < 31) load_kv(k0 + 64, sel ^ 1);
        __syncthreads();
    }

    const float inv0 = 1.f / l0;
    const float inv1 = 1.f / l1;
    float* Op0 = AO + ((size_t)b * Ss + qrow) * 512 + h * 64;
    float* Op1 = Op0 + (size_t)8 * 512;
    #pragma unroll
    for (int df = 0; df < 8; df++) {
        float2 o0 = { O[df][0] * inv0, O[df][1] * inv0 };
        float2 o1 = { O[df][2] * inv1, O[df][3] * inv1 };
        *(float2*)(Op0 + df * 8 + 2 * tig) = o0;
        *(float2*)(Op1 + df * 8 + 2 * tig) = o1;
    }
}

// ===========================================================================
// Residual + LayerNorm
// ===========================================================================
__global__ __launch_bounds__(512)
void ln_kernel(const float* __restrict__ q, const float* __restrict__ gamma,
               const float* __restrict__ beta, float* __restrict__ out) {
    __shared__ float rs[16], rs2[16];
    const int r = blockIdx.x;
    const int j = threadIdx.x;

    const float v = q[(size_t)r * 512 + j] + g_P[(size_t)r * 512 + j];

    float s = v, s2 = v * v;
    #pragma unroll
    for (int o = 16; o > 0; o >>= 1) {
        s  += __shfl_xor_sync(0xffffffffu, s,  o);
        s2 += __shfl_xor_sync(0xffffffffu, s2, o);
    }
    const int w = j >> 5, ln = j & 31;
    if (ln == 0) { rs[w] = s; rs2[w] = s2; }
    __syncthreads();
    if (w == 0) {
        s  = (ln < 16) ? rs[ln]  : 0.f;
        s2 = (ln < 16) ? rs2[ln] : 0.f;
        #pragma unroll
        for (int o = 8; o > 0; o >>= 1) {
            s  += __shfl_xor_sync(0xffffffffu, s,  o);
            s2 += __shfl_xor_sync(0xffffffffu, s2, o);
        }
        if (ln == 0) { rs[0] = s; rs2[0] = s2; }
    }
    __syncthreads();

    const float mu  = rs[0] * (1.f / 512.f);
    const float var = rs2[0] * (1.f / 512.f) - mu * mu;
    const float inv = rsqrtf(var + 1e-5f);
    out[(size_t)r * 512 + j] = (v - mu) * inv * gamma[j] + beta[j];
}

// ===========================================================================
extern "C" void kernel_launch(void* const* d_in, const int* in_sizes, int n_in,
                              void* d_out, int out_size) {
    const float* q     = (const float*)d_in[0];
    const float* k     = (const float*)d_in[1];
    const float* v     = (const float*)d_in[2];
    const float* mask  = (const float*)d_in[3];
    const float* Wq    = (const float*)d_in[4];
    const float* bq    = (const float*)d_in[5];
    const float* Wk    = (const float*)d_in[6];
    const float* bk    = (const float*)d_in[7];
    const float* Wv    = (const float*)d_in[8];
    const float* bv    = (const float*)d_in[9];
    const float* Wo    = (const float*)d_in[10];
    const float* bo    = (const float*)d_in[11];
    const float* gamma = (const float*)d_in[12];
    const float* beta  = (const float*)d_in[13];
    float* out = (float*)d_out;

    float *gQ, *gK, *gV, *gAO, *gP;
    cudaGetSymbolAddress((void**)&gQ,  g_Q);
    cudaGetSymbolAddress((void**)&gK,  g_K);
    cudaGetSymbolAddress((void**)&gV,  g_V);
    cudaGetSymbolAddress((void**)&gAO, g_AO);
    cudaGetSymbolAddress((void**)&gP,  g_P);

    cudaFuncSetAttribute(attn_mma_kernel,
                         cudaFuncAttributeMaxDynamicSharedMemorySize,
                         ATTN_SMEM_BYTES);

    dim3 gg(MROWS / 128, 512 / 128);
    gemm_tc_kernel<<<gg, 256>>>(q, Wq, bq, gQ);
    gemm_tc_kernel<<<gg, 256>>>(k, Wk, bk, gK);
    gemm_tc_kernel<<<gg, 256>>>(v, Wv, bv, gV);

    attn_mma_kernel<<<dim3(Ss / 128, Bb * Hh), 256, ATTN_SMEM_BYTES>>>(gQ, gK, gV, mask, gAO);

    gemm_tc_kernel<<<gg, 256>>>(gAO, Wo, bo, gP);

    ln_kernel<<<MROWS, 512>>>(q, gamma, beta, out);
}

// round 6
// speedup vs baseline: 6.6130x; 1.2195x over previous
#include <cuda_runtime.h>
#include <cstddef>
#include <cstdint>

#define Bb   4
#define Ss   2048
#define DIN  512
#define Hh   8
#define DM   512
#define MROWS (Bb*Ss)          // 8192

// Scratch (device globals: allocation-free rule)
__device__ float g_Q [MROWS*DM];
__device__ float g_K [MROWS*DM];
__device__ float g_V [MROWS*DM];
__device__ float g_AO[MROWS*DM];
__device__ float g_P [MROWS*DIN];

// ===========================================================================
// helpers
// ===========================================================================
__device__ __forceinline__ uint32_t f2tf32(float f) {
    uint32_t r;
    asm("cvt.rna.tf32.f32 %0, %1;" : "=r"(r) : "f"(f));
    return r;
}

// D += A * B  (m16n8k8, tf32 inputs, fp32 accum). row.col.
__device__ __forceinline__ void mma_tf32(float* d, const uint32_t* a,
                                         uint32_t b0, uint32_t b1) {
    asm volatile(
        "mma.sync.aligned.m16n8k8.row.col.f32.tf32.tf32.f32 "
        "{%0,%1,%2,%3}, {%4,%5,%6,%7}, {%8,%9}, {%0,%1,%2,%3};"
        : "+f"(d[0]), "+f"(d[1]), "+f"(d[2]), "+f"(d[3])
        : "r"(a[0]), "r"(a[1]), "r"(a[2]), "r"(a[3]), "r"(b0), "r"(b1));
}

// ===========================================================================
// Tensor-core GEMM (proven R5 version, unchanged)
// ===========================================================================
#define XS_STR 36
#define WS_STR 136

__global__ __launch_bounds__(256)
void gemm_tc_kernel(const float* __restrict__ X, const float* __restrict__ W,
                    const float* __restrict__ bias, float* __restrict__ C) {
    __shared__ float Xs[128 * XS_STR];
    __shared__ float Ws[32 * WS_STR];

    const int tid  = threadIdx.x;
    const int lane = tid & 31;
    const int wid  = tid >> 5;
    const int gid  = lane >> 2;
    const int tig  = lane & 3;

    const int warp_m = wid >> 2;
    const int warp_n = wid & 3;
    const int m_base = warp_m * 64;
    const int n_base = warp_n * 32;

    const int bm = blockIdx.x * 128;
    const int bn = blockIdx.y * 128;

    float acc[4][4][4];
    #pragma unroll
    for (int mf = 0; mf < 4; mf++)
        #pragma unroll
        for (int nf = 0; nf < 4; nf++)
            #pragma unroll
            for (int c = 0; c < 4; c++) acc[mf][nf][c] = 0.f;

    for (int k0 = 0; k0 < 512; k0 += 32) {
        #pragma unroll
        for (int l = 0; l < 4; l++) {
            int e = tid + l * 256;
            int r = e >> 3, c4 = e & 7;
            float4 v = *(const float4*)(X + (size_t)(bm + r) * 512 + k0 + c4 * 4);
            uint4 t = { f2tf32(v.x), f2tf32(v.y), f2tf32(v.z), f2tf32(v.w) };
            *(uint4*)(Xs + r * XS_STR + c4 * 4) = t;
        }
        #pragma unroll
        for (int l = 0; l < 4; l++) {
            int e = tid + l * 256;
            int r = e >> 5, c4 = e & 31;
            float4 v = *(const float4*)(W + (size_t)(k0 + r) * 512 + bn + c4 * 4);
            uint4 t = { f2tf32(v.x), f2tf32(v.y), f2tf32(v.z), f2tf32(v.w) };
            *(uint4*)(Ws + r * WS_STR + c4 * 4) = t;
        }
        __syncthreads();

        #pragma unroll
        for (int ks = 0; ks < 4; ks++) {
            const int kk = ks * 8;
            uint32_t A[4][4];
            #pragma unroll
            for (int mf = 0; mf < 4; mf++) {
                const float* ap = Xs + (m_base + mf * 16 + gid) * XS_STR + kk + tig;
                A[mf][0] = __float_as_uint(ap[0]);
                A[mf][1] = __float_as_uint(ap[8 * XS_STR]);
                A[mf][2] = __float_as_uint(ap[4]);
                A[mf][3] = __float_as_uint(ap[8 * XS_STR + 4]);
            }
            #pragma unroll
            for (int nf = 0; nf < 4; nf++) {
                const float* bp = Ws + (kk + tig) * WS_STR + n_base + nf * 8 + gid;
                uint32_t b0 = __float_as_uint(bp[0]);
                uint32_t b1 = __float_as_uint(bp[4 * WS_STR]);
                #pragma unroll
                for (int mf = 0; mf < 4; mf++)
                    mma_tf32(acc[mf][nf], A[mf], b0, b1);
            }
        }
        __syncthreads();
    }

    #pragma unroll
    for (int nf = 0; nf < 4; nf++) {
        const int col = bn + n_base + nf * 8 + 2 * tig;
        float2 b2 = *(const float2*)(bias + col);
        #pragma unroll
        for (int mf = 0; mf < 4; mf++) {
            const int row0 = bm + m_base + mf * 16 + gid;
            float2 o0 = { acc[mf][nf][0] + b2.x, acc[mf][nf][1] + b2.y };
            float2 o1 = { acc[mf][nf][2] + b2.x, acc[mf][nf][3] + b2.y };
            *(float2*)(C + (size_t)row0 * 512 + col) = o0;
            *(float2*)(C + (size_t)(row0 + 8) * 512 + col) = o1;
        }
    }
}

// ===========================================================================
// mma.sync tf32 flash attention, v2.
// 1 CTA = (b,h), 128 q-rows, 8 warps. 32-key tiles, double-buffered K/V.
// K stride 68 (4g+t banks), V stride 72 (8t+g banks): conflict-free frag LDS.
// P never touches smem: S C-frag -> PV A-frag via quad shuffle transpose.
// 35.8 KB static smem + <=128 regs => 2 CTAs/SM.
// ===========================================================================
#define KSTR 68
#define VSTR 72
#define SM_K0 0
#define SM_K1 (32*KSTR)
#define SM_V0 (2*32*KSTR)
#define SM_V1 (SM_V0 + 32*VSTR)
#define ATTN_SMEM_FLOATS (SM_V0 + 2*32*VSTR)   // 8960 floats = 35840 B

__global__ __launch_bounds__(256, 2)
void attn_mma_kernel(const float* __restrict__ Qg, const float* __restrict__ Kg,
                     const float* __restrict__ Vg, const float* __restrict__ mask,
                     float* __restrict__ AO) {
    __shared__ float sm[ATTN_SMEM_FLOATS];
    const int tid  = threadIdx.x;
    const int lane = tid & 31;
    const int wid  = tid >> 5;
    const int gid  = lane >> 2;
    const int tig  = lane & 3;
    const int srcA = (lane & ~3) | (tig >> 1);   // quad transpose source lanes
    const int srcB = srcA + 2;
    const bool odd = (tig & 1);

    const int bh = blockIdx.y;
    const int b  = bh >> 3;
    const int h  = bh & 7;
    const int q0 = blockIdx.x * 128;

    const float* Kb = Kg + (size_t)b * Ss * 512 + h * 64;
    const float* Vb = Vg + (size_t)b * Ss * 512 + h * 64;

    // persistent Q A-fragments (pre-scaled 1/8, tf32)
    const int qrow = q0 + wid * 16 + gid;
    const float* Qp = Qg + ((size_t)b * Ss + qrow) * 512 + h * 64;
    uint32_t Qa[8][4];
    #pragma unroll
    for (int ch = 0; ch < 8; ch++) {
        Qa[ch][0] = f2tf32(Qp[ch * 8 + tig] * 0.125f);
        Qa[ch][1] = f2tf32(Qp[8 * 512 + ch * 8 + tig] * 0.125f);
        Qa[ch][2] = f2tf32(Qp[ch * 8 + tig + 4] * 0.125f);
        Qa[ch][3] = f2tf32(Qp[8 * 512 + ch * 8 + tig + 4] * 0.125f);
    }

    // K/V 32-key tile loader (tf32-converted)
    auto load_kv = [&](int k0, int sel) {
        float* Ks = sm + (sel ? SM_K1 : SM_K0);
        float* Vs = sm + (sel ? SM_V1 : SM_V0);
        #pragma unroll
        for (int l = 0; l < 2; l++) {
            int e = tid + l * 256;          // 0..511
            int r = e >> 4, c4 = e & 15;    // 32 rows x 16 float4
            float4 kv = *(const float4*)(Kb + (size_t)(k0 + r) * 512 + c4 * 4);
            uint4 tk = { f2tf32(kv.x), f2tf32(kv.y), f2tf32(kv.z), f2tf32(kv.w) };
            *(uint4*)(Ks + r * KSTR + c4 * 4) = tk;
            float4 vv = *(const float4*)(Vb + (size_t)(k0 + r) * 512 + c4 * 4);
            uint4 tv = { f2tf32(vv.x), f2tf32(vv.y), f2tf32(vv.z), f2tf32(vv.w) };
            *(uint4*)(Vs + r * VSTR + c4 * 4) = tv;
        }
    };

    load_kv(0, 0);

    const float* Mrow0 = mask + (size_t)b * Ss * Ss + (size_t)qrow * Ss;
    const float* Mrow1 = Mrow0 + (size_t)8 * Ss;

    float m0 = -1e30f, m1 = -1e30f, l0 = 0.f, l1 = 0.f;
    float O[8][4];
    #pragma unroll
    for (int j = 0; j < 8; j++)
        #pragma unroll
        for (int c = 0; c < 4; c++) O[j][c] = 0.f;

    __syncthreads();

    for (int kt = 0; kt < 64; kt++) {
        const int sel = kt & 1;
        const int k0  = kt * 32;
        const float* Ks = sm + (sel ? SM_K1 : SM_K0);
        const float* Vs = sm + (sel ? SM_V1 : SM_V0);

        // ---- S = Q K^T : 4 key-frags x 8 d-chunks ----
        float S[4][4];
        #pragma unroll
        for (int kf = 0; kf < 4; kf++) {
            S[kf][0] = 0.f; S[kf][1] = 0.f; S[kf][2] = 0.f; S[kf][3] = 0.f;
            #pragma unroll
            for (int ch = 0; ch < 8; ch++) {
                const float* kp = Ks + (kf * 8 + gid) * KSTR + ch * 8 + tig;
                uint32_t b0 = __float_as_uint(kp[0]);
                uint32_t b1 = __float_as_uint(kp[4]);
                mma_tf32(S[kf], Qa[ch], b0, b1);
            }
        }

        // ---- mask * s, threshold, row max ----
        float mx0 = m0, mx1 = m1;
        #pragma unroll
        for (int kf = 0; kf < 4; kf++) {
            float2 mk0 = *(const float2*)(Mrow0 + k0 + kf * 8 + 2 * tig);
            float2 mk1 = *(const float2*)(Mrow1 + k0 + kf * 8 + 2 * tig);
            float s0 = S[kf][0] * mk0.x;
            float s1 = S[kf][1] * mk0.y;
            float s2 = S[kf][2] * mk1.x;
            float s3 = S[kf][3] * mk1.y;
            s0 = (s0 > 0.f) ? s0 : -10000.f;
            s1 = (s1 > 0.f) ? s1 : -10000.f;
            s2 = (s2 > 0.f) ? s2 : -10000.f;
            s3 = (s3 > 0.f) ? s3 : -10000.f;
            S[kf][0] = s0; S[kf][1] = s1; S[kf][2] = s2; S[kf][3] = s3;
            mx0 = fmaxf(mx0, fmaxf(s0, s1));
            mx1 = fmaxf(mx1, fmaxf(s2, s3));
        }
        mx0 = fmaxf(mx0, __shfl_xor_sync(0xffffffffu, mx0, 1));
        mx0 = fmaxf(mx0, __shfl_xor_sync(0xffffffffu, mx0, 2));
        mx1 = fmaxf(mx1, __shfl_xor_sync(0xffffffffu, mx1, 1));
        mx1 = fmaxf(mx1, __shfl_xor_sync(0xffffffffu, mx1, 2));

        // ---- exp (store P back into S regs, tf32) ----
        float f0 = __expf(m0 - mx0);
        float f1 = __expf(m1 - mx1);
        float sum0 = 0.f, sum1 = 0.f;
        #pragma unroll
        for (int kf = 0; kf < 4; kf++) {
            float p0 = __expf(S[kf][0] - mx0);
            float p1 = __expf(S[kf][1] - mx0);
            float p2 = __expf(S[kf][2] - mx1);
            float p3 = __expf(S[kf][3] - mx1);
            sum0 += p0 + p1;
            sum1 += p2 + p3;
            S[kf][0] = __uint_as_float(f2tf32(p0));
            S[kf][1] = __uint_as_float(f2tf32(p1));
            S[kf][2] = __uint_as_float(f2tf32(p2));
            S[kf][3] = __uint_as_float(f2tf32(p3));
        }
        sum0 += __shfl_xor_sync(0xffffffffu, sum0, 1);
        sum0 += __shfl_xor_sync(0xffffffffu, sum0, 2);
        sum1 += __shfl_xor_sync(0xffffffffu, sum1, 1);
        sum1 += __shfl_xor_sync(0xffffffffu, sum1, 2);

        l0 = l0 * f0 + sum0;  m0 = mx0;
        l1 = l1 * f1 + sum1;  m1 = mx1;

        #pragma unroll
        for (int j = 0; j < 8; j++) {
            O[j][0] *= f0; O[j][1] *= f0;
            O[j][2] *= f1; O[j][3] *= f1;
        }

        // ---- prefetch next tile (other buffer; overlaps with PV) ----
        if (kt < 63) load_kv(k0 + 32, sel ^ 1);

        // ---- O += P @ V : A-frags via quad shuffle transpose ----
        #pragma unroll
        for (int kc = 0; kc < 4; kc++) {
            float x0 = __shfl_sync(0xffffffffu, S[kc][0], srcA);
            float x1 = __shfl_sync(0xffffffffu, S[kc][1], srcA);
            float y0 = __shfl_sync(0xffffffffu, S[kc][2], srcA);
            float y1 = __shfl_sync(0xffffffffu, S[kc][3], srcA);
            float z0 = __shfl_sync(0xffffffffu, S[kc][0], srcB);
            float z1 = __shfl_sync(0xffffffffu, S[kc][1], srcB);
            float w0 = __shfl_sync(0xffffffffu, S[kc][2], srcB);
            float w1 = __shfl_sync(0xffffffffu, S[kc][3], srcB);
            uint32_t A[4];
            A[0] = __float_as_uint(odd ? x1 : x0);
            A[1] = __float_as_uint(odd ? y1 : y0);
            A[2] = __float_as_uint(odd ? z1 : z0);
            A[3] = __float_as_uint(odd ? w1 : w0);
            #pragma unroll
            for (int df = 0; df < 8; df++) {
                const float* vp = Vs + (kc * 8 + tig) * VSTR + df * 8 + gid;
                uint32_t b0 = __float_as_uint(vp[0]);
                uint32_t b1 = __float_as_uint(vp[4 * VSTR]);
                mma_tf32(O[df], A, b0, b1);
            }
        }

        __syncthreads();
    }

    // ---- epilogue: normalize + write ----
    const float inv0 = 1.f / l0;
    const float inv1 = 1.f / l1;
    float* Op0 = AO + ((size_t)b * Ss + qrow) * 512 + h * 64;
    float* Op1 = Op0 + (size_t)8 * 512;
    #pragma unroll
    for (int df = 0; df < 8; df++) {
        float2 o0 = { O[df][0] * inv0, O[df][1] * inv0 };
        float2 o1 = { O[df][2] * inv1, O[df][3] * inv1 };
        *(float2*)(Op0 + df * 8 + 2 * tig) = o0;
        *(float2*)(Op1 + df * 8 + 2 * tig) = o1;
    }
}

// ===========================================================================
// Residual + LayerNorm
// ===========================================================================
__global__ __launch_bounds__(512)
void ln_kernel(const float* __restrict__ q, const float* __restrict__ gamma,
               const float* __restrict__ beta, float* __restrict__ out) {
    __shared__ float rs[16], rs2[16];
    const int r = blockIdx.x;
    const int j = threadIdx.x;

    const float v = q[(size_t)r * 512 + j] + g_P[(size_t)r * 512 + j];

    float s = v, s2 = v * v;
    #pragma unroll
    for (int o = 16; o > 0; o >>= 1) {
        s  += __shfl_xor_sync(0xffffffffu, s,  o);
        s2 += __shfl_xor_sync(0xffffffffu, s2, o);
    }
    const int w = j >> 5, ln = j & 31;
    if (ln == 0) { rs[w] = s; rs2[w] = s2; }
    __syncthreads();
    if (w == 0) {
        s  = (ln < 16) ? rs[ln]  : 0.f;
        s2 = (ln < 16) ? rs2[ln] : 0.f;
        #pragma unroll
        for (int o = 8; o > 0; o >>= 1) {
            s  += __shfl_xor_sync(0xffffffffu, s,  o);
            s2 += __shfl_xor_sync(0xffffffffu, s2, o);
        }
        if (ln == 0) { rs[0] = s; rs2[0] = s2; }
    }
    __syncthreads();

    const float mu  = rs[0] * (1.f / 512.f);
    const float var = rs2[0] * (1.f / 512.f) - mu * mu;
    const float inv = rsqrtf(var + 1e-5f);
    out[(size_t)r * 512 + j] = (v - mu) * inv * gamma[j] + beta[j];
}

// ===========================================================================
extern "C" void kernel_launch(void* const* d_in, const int* in_sizes, int n_in,
                              void* d_out, int out_size) {
    const float* q     = (const float*)d_in[0];
    const float* k     = (const float*)d_in[1];
    const float* v     = (const float*)d_in[2];
    const float* mask  = (const float*)d_in[3];
    const float* Wq    = (const float*)d_in[4];
    const float* bq    = (const float*)d_in[5];
    const float* Wk    = (const float*)d_in[6];
    const float* bk    = (const float*)d_in[7];
    const float* Wv    = (const float*)d_in[8];
    const float* bv    = (const float*)d_in[9];
    const float* Wo    = (const float*)d_in[10];
    const float* bo    = (const float*)d_in[11];
    const float* gamma = (const float*)d_in[12];
    const float* beta  = (const float*)d_in[13];
    float* out = (float*)d_out;

    float *gQ, *gK, *gV, *gAO, *gP;
    cudaGetSymbolAddress((void**)&gQ,  g_Q);
    cudaGetSymbolAddress((void**)&gK,  g_K);
    cudaGetSymbolAddress((void**)&gV,  g_V);
    cudaGetSymbolAddress((void**)&gAO, g_AO);
    cudaGetSymbolAddress((void**)&gP,  g_P);

    dim3 gg(MROWS / 128, 512 / 128);
    gemm_tc_kernel<<<gg, 256>>>(q, Wq, bq, gQ);
    gemm_tc_kernel<<<gg, 256>>>(k, Wk, bk, gK);
    gemm_tc_kernel<<<gg, 256>>>(v, Wv, bv, gV);

    attn_mma_kernel<<<dim3(Ss / 128, Bb * Hh), 256>>>(gQ, gK, gV, mask, gAO);

    gemm_tc_kernel<<<gg, 256>>>(gAO, Wo, bo, gP);

    ln_kernel<<<MROWS, 512>>>(q, gamma, beta, out);
}

// round 7
// speedup vs baseline: 6.9521x; 1.0513x over previous
#include <cuda_runtime.h>
#include <cstddef>
#include <cstdint>

#define Bb   4
#define Ss   2048
#define DIN  512
#define Hh   8
#define DM   512
#define MROWS (Bb*Ss)          // 8192

// Scratch (device globals: allocation-free rule)
__device__ float g_Q [MROWS*DM];
__device__ float g_K [MROWS*DM];
__device__ float g_V [MROWS*DM];
__device__ float g_AO[MROWS*DM];
__device__ float g_P [MROWS*DIN];

// ===========================================================================
// helpers
// ===========================================================================
__device__ __forceinline__ uint32_t f2tf32(float f) {
    uint32_t r;
    asm("cvt.rna.tf32.f32 %0, %1;" : "=r"(r) : "f"(f));
    return r;
}

// D += A * B  (m16n8k8, tf32 inputs, fp32 accum). row.col.
__device__ __forceinline__ void mma_tf32(float* d, const uint32_t* a,
                                         uint32_t b0, uint32_t b1) {
    asm volatile(
        "mma.sync.aligned.m16n8k8.row.col.f32.tf32.tf32.f32 "
        "{%0,%1,%2,%3}, {%4,%5,%6,%7}, {%8,%9}, {%0,%1,%2,%3};"
        : "+f"(d[0]), "+f"(d[1]), "+f"(d[2]), "+f"(d[3])
        : "r"(a[0]), "r"(a[1]), "r"(a[2]), "r"(a[3]), "r"(b0), "r"(b1));
}

__device__ __forceinline__ void ldsm_x4(uint32_t* r, uint32_t addr) {
    asm volatile("ldmatrix.sync.aligned.m8n8.x4.shared.b16 {%0,%1,%2,%3}, [%4];"
                 : "=r"(r[0]), "=r"(r[1]), "=r"(r[2]), "=r"(r[3]) : "r"(addr));
}

// ===========================================================================
// Tensor-core GEMM (proven R5 version, unchanged)
// ===========================================================================
#define XS_STR 36
#define WS_STR 136

__global__ __launch_bounds__(256)
void gemm_tc_kernel(const float* __restrict__ X, const float* __restrict__ W,
                    const float* __restrict__ bias, float* __restrict__ C) {
    __shared__ float Xs[128 * XS_STR];
    __shared__ float Ws[32 * WS_STR];

    const int tid  = threadIdx.x;
    const int lane = tid & 31;
    const int wid  = tid >> 5;
    const int gid  = lane >> 2;
    const int tig  = lane & 3;

    const int warp_m = wid >> 2;
    const int warp_n = wid & 3;
    const int m_base = warp_m * 64;
    const int n_base = warp_n * 32;

    const int bm = blockIdx.x * 128;
    const int bn = blockIdx.y * 128;

    float acc[4][4][4];
    #pragma unroll
    for (int mf = 0; mf < 4; mf++)
        #pragma unroll
        for (int nf = 0; nf < 4; nf++)
            #pragma unroll
            for (int c = 0; c < 4; c++) acc[mf][nf][c] = 0.f;

    for (int k0 = 0; k0 < 512; k0 += 32) {
        #pragma unroll
        for (int l = 0; l < 4; l++) {
            int e = tid + l * 256;
            int r = e >> 3, c4 = e & 7;
            float4 v = *(const float4*)(X + (size_t)(bm + r) * 512 + k0 + c4 * 4);
            uint4 t = { f2tf32(v.x), f2tf32(v.y), f2tf32(v.z), f2tf32(v.w) };
            *(uint4*)(Xs + r * XS_STR + c4 * 4) = t;
        }
        #pragma unroll
        for (int l = 0; l < 4; l++) {
            int e = tid + l * 256;
            int r = e >> 5, c4 = e & 31;
            float4 v = *(const float4*)(W + (size_t)(k0 + r) * 512 + bn + c4 * 4);
            uint4 t = { f2tf32(v.x), f2tf32(v.y), f2tf32(v.z), f2tf32(v.w) };
            *(uint4*)(Ws + r * WS_STR + c4 * 4) = t;
        }
        __syncthreads();

        #pragma unroll
        for (int ks = 0; ks < 4; ks++) {
            const int kk = ks * 8;
            uint32_t A[4][4];
            #pragma unroll
            for (int mf = 0; mf < 4; mf++) {
                const float* ap = Xs + (m_base + mf * 16 + gid) * XS_STR + kk + tig;
                A[mf][0] = __float_as_uint(ap[0]);
                A[mf][1] = __float_as_uint(ap[8 * XS_STR]);
                A[mf][2] = __float_as_uint(ap[4]);
                A[mf][3] = __float_as_uint(ap[8 * XS_STR + 4]);
            }
            #pragma unroll
            for (int nf = 0; nf < 4; nf++) {
                const float* bp = Ws + (kk + tig) * WS_STR + n_base + nf * 8 + gid;
                uint32_t b0 = __float_as_uint(bp[0]);
                uint32_t b1 = __float_as_uint(bp[4 * WS_STR]);
                #pragma unroll
                for (int mf = 0; mf < 4; mf++)
                    mma_tf32(acc[mf][nf], A[mf], b0, b1);
            }
        }
        __syncthreads();
    }

    #pragma unroll
    for (int nf = 0; nf < 4; nf++) {
        const int col = bn + n_base + nf * 8 + 2 * tig;
        float2 b2 = *(const float2*)(bias + col);
        #pragma unroll
        for (int mf = 0; mf < 4; mf++) {
            const int row0 = bm + m_base + mf * 16 + gid;
            float2 o0 = { acc[mf][nf][0] + b2.x, acc[mf][nf][1] + b2.y };
            float2 o1 = { acc[mf][nf][2] + b2.x, acc[mf][nf][3] + b2.y };
            *(float2*)(C + (size_t)row0 * 512 + col) = o0;
            *(float2*)(C + (size_t)(row0 + 8) * 512 + col) = o1;
        }
    }
}

// ===========================================================================
// mma.sync tf32 flash attention, v3.
// v2 + : K B-frags via ldmatrix.x4 (conflict-free, KSTR=68),
//        mask prefetched into regs before S-MMAs,
//        next-tile global prefetch moved before softmax.
// ===========================================================================
#define KSTR 68
#define VSTR 72
#define SM_K0 0
#define SM_K1 (32*KSTR)
#define SM_V0 (2*32*KSTR)
#define SM_V1 (SM_V0 + 32*VSTR)
#define ATTN_SMEM_FLOATS (SM_V0 + 2*32*VSTR)   // 8960 floats = 35840 B

__global__ __launch_bounds__(256, 2)
void attn_mma_kernel(const float* __restrict__ Qg, const float* __restrict__ Kg,
                     const float* __restrict__ Vg, const float* __restrict__ mask,
                     float* __restrict__ AO) {
    __shared__ float sm[ATTN_SMEM_FLOATS];
    const int tid  = threadIdx.x;
    const int lane = tid & 31;
    const int wid  = tid >> 5;
    const int gid  = lane >> 2;
    const int tig  = lane & 3;
    const int srcA = (lane & ~3) | (tig >> 1);   // quad transpose source lanes
    const int srcB = srcA + 2;
    const bool odd = (tig & 1);

    // ldmatrix per-lane base (floats): row = lane&7, +4 for b1, +8 for ch-pair hi
    const int lm_base = (lane & 7) * KSTR + ((lane >> 3) & 1) * 4 + (lane >> 4) * 8;
    const uint32_t smK0_u = (uint32_t)__cvta_generic_to_shared(sm + SM_K0);
    const uint32_t smK1_u = (uint32_t)__cvta_generic_to_shared(sm + SM_K1);

    const int bh = blockIdx.y;
    const int b  = bh >> 3;
    const int h  = bh & 7;
    const int q0 = blockIdx.x * 128;

    const float* Kb = Kg + (size_t)b * Ss * 512 + h * 64;
    const float* Vb = Vg + (size_t)b * Ss * 512 + h * 64;

    // persistent Q A-fragments (pre-scaled 1/8, tf32)
    const int qrow = q0 + wid * 16 + gid;
    const float* Qp = Qg + ((size_t)b * Ss + qrow) * 512 + h * 64;
    uint32_t Qa[8][4];
    #pragma unroll
    for (int ch = 0; ch < 8; ch++) {
        Qa[ch][0] = f2tf32(Qp[ch * 8 + tig] * 0.125f);
        Qa[ch][1] = f2tf32(Qp[8 * 512 + ch * 8 + tig] * 0.125f);
        Qa[ch][2] = f2tf32(Qp[ch * 8 + tig + 4] * 0.125f);
        Qa[ch][3] = f2tf32(Qp[8 * 512 + ch * 8 + tig + 4] * 0.125f);
    }

    // K/V 32-key tile loader (tf32-converted)
    auto load_kv = [&](int k0, int sel) {
        float* Ks = sm + (sel ? SM_K1 : SM_K0);
        float* Vs = sm + (sel ? SM_V1 : SM_V0);
        #pragma unroll
        for (int l = 0; l < 2; l++) {
            int e = tid + l * 256;          // 0..511
            int r = e >> 4, c4 = e & 15;    // 32 rows x 16 float4
            float4 kv = *(const float4*)(Kb + (size_t)(k0 + r) * 512 + c4 * 4);
            uint4 tk = { f2tf32(kv.x), f2tf32(kv.y), f2tf32(kv.z), f2tf32(kv.w) };
            *(uint4*)(Ks + r * KSTR + c4 * 4) = tk;
            float4 vv = *(const float4*)(Vb + (size_t)(k0 + r) * 512 + c4 * 4);
            uint4 tv = { f2tf32(vv.x), f2tf32(vv.y), f2tf32(vv.z), f2tf32(vv.w) };
            *(uint4*)(Vs + r * VSTR + c4 * 4) = tv;
        }
    };

    load_kv(0, 0);

    const float* Mrow0 = mask + (size_t)b * Ss * Ss + (size_t)qrow * Ss;
    const float* Mrow1 = Mrow0 + (size_t)8 * Ss;

    float m0 = -1e30f, m1 = -1e30f, l0 = 0.f, l1 = 0.f;
    float O[8][4];
    #pragma unroll
    for (int j = 0; j < 8; j++)
        #pragma unroll
        for (int c = 0; c < 4; c++) O[j][c] = 0.f;

    __syncthreads();

    for (int kt = 0; kt < 64; kt++) {
        const int sel = kt & 1;
        const int k0  = kt * 32;
        const float* Vs = sm + (sel ? SM_V1 : SM_V0);
        const uint32_t smK_u = sel ? smK1_u : smK0_u;

        // ---- prefetch mask into regs (latency hidden under S-MMAs) ----
        float2 mk0[4], mk1[4];
        #pragma unroll
        for (int kf = 0; kf < 4; kf++) {
            mk0[kf] = *(const float2*)(Mrow0 + k0 + kf * 8 + 2 * tig);
            mk1[kf] = *(const float2*)(Mrow1 + k0 + kf * 8 + 2 * tig);
        }

        // ---- S = Q K^T : 4 key-frags x 4 ldmatrix.x4 (8 d-chunks) ----
        float S[4][4];
        #pragma unroll
        for (int kf = 0; kf < 4; kf++) {
            S[kf][0] = 0.f; S[kf][1] = 0.f; S[kf][2] = 0.f; S[kf][3] = 0.f;
            #pragma unroll
            for (int ch2 = 0; ch2 < 4; ch2++) {
                uint32_t r[4];
                ldsm_x4(r, smK_u + 4u * (uint32_t)(kf * 8 * KSTR + ch2 * 16 + lm_base));
                mma_tf32(S[kf], Qa[2 * ch2],     r[0], r[1]);
                mma_tf32(S[kf], Qa[2 * ch2 + 1], r[2], r[3]);
            }
        }

        // ---- prefetch next K/V tile (overlaps softmax below) ----
        if (kt < 63) load_kv(k0 + 32, sel ^ 1);

        // ---- mask * s, threshold, row max ----
        float mx0 = m0, mx1 = m1;
        #pragma unroll
        for (int kf = 0; kf < 4; kf++) {
            float s0 = S[kf][0] * mk0[kf].x;
            float s1 = S[kf][1] * mk0[kf].y;
            float s2 = S[kf][2] * mk1[kf].x;
            float s3 = S[kf][3] * mk1[kf].y;
            s0 = (s0 > 0.f) ? s0 : -10000.f;
            s1 = (s1 > 0.f) ? s1 : -10000.f;
            s2 = (s2 > 0.f) ? s2 : -10000.f;
            s3 = (s3 > 0.f) ? s3 : -10000.f;
            S[kf][0] = s0; S[kf][1] = s1; S[kf][2] = s2; S[kf][3] = s3;
            mx0 = fmaxf(mx0, fmaxf(s0, s1));
            mx1 = fmaxf(mx1, fmaxf(s2, s3));
        }
        mx0 = fmaxf(mx0, __shfl_xor_sync(0xffffffffu, mx0, 1));
        mx0 = fmaxf(mx0, __shfl_xor_sync(0xffffffffu, mx0, 2));
        mx1 = fmaxf(mx1, __shfl_xor_sync(0xffffffffu, mx1, 1));
        mx1 = fmaxf(mx1, __shfl_xor_sync(0xffffffffu, mx1, 2));

        // ---- exp (store P back into S regs, tf32) ----
        float f0 = __expf(m0 - mx0);
        float f1 = __expf(m1 - mx1);
        float sum0 = 0.f, sum1 = 0.f;
        #pragma unroll
        for (int kf = 0; kf < 4; kf++) {
            float p0 = __expf(S[kf][0] - mx0);
            float p1 = __expf(S[kf][1] - mx0);
            float p2 = __expf(S[kf][2] - mx1);
            float p3 = __expf(S[kf][3] - mx1);
            sum0 += p0 + p1;
            sum1 += p2 + p3;
            S[kf][0] = __uint_as_float(f2tf32(p0));
            S[kf][1] = __uint_as_float(f2tf32(p1));
            S[kf][2] = __uint_as_float(f2tf32(p2));
            S[kf][3] = __uint_as_float(f2tf32(p3));
        }
        sum0 += __shfl_xor_sync(0xffffffffu, sum0, 1);
        sum0 += __shfl_xor_sync(0xffffffffu, sum0, 2);
        sum1 += __shfl_xor_sync(0xffffffffu, sum1, 1);
        sum1 += __shfl_xor_sync(0xffffffffu, sum1, 2);

        l0 = l0 * f0 + sum0;  m0 = mx0;
        l1 = l1 * f1 + sum1;  m1 = mx1;

        #pragma unroll
        for (int j = 0; j < 8; j++) {
            O[j][0] *= f0; O[j][1] *= f0;
            O[j][2] *= f1; O[j][3] *= f1;
        }

        // ---- O += P @ V : A-frags via quad shuffle transpose ----
        #pragma unroll
        for (int kc = 0; kc < 4; kc++) {
            float x0 = __shfl_sync(0xffffffffu, S[kc][0], srcA);
            float x1 = __shfl_sync(0xffffffffu, S[kc][1], srcA);
            float y0 = __shfl_sync(0xffffffffu, S[kc][2], srcA);
            float y1 = __shfl_sync(0xffffffffu, S[kc][3], srcA);
            float z0 = __shfl_sync(0xffffffffu, S[kc][0], srcB);
            float z1 = __shfl_sync(0xffffffffu, S[kc][1], srcB);
            float w0 = __shfl_sync(0xffffffffu, S[kc][2], srcB);
            float w1 = __shfl_sync(0xffffffffu, S[kc][3], srcB);
            uint32_t A[4];
            A[0] = __float_as_uint(odd ? x1 : x0);
            A[1] = __float_as_uint(odd ? y1 : y0);
            A[2] = __float_as_uint(odd ? z1 : z0);
            A[3] = __float_as_uint(odd ? w1 : w0);
            #pragma unroll
            for (int df = 0; df < 8; df++) {
                const float* vp = Vs + (kc * 8 + tig) * VSTR + df * 8 + gid;
                uint32_t b0 = __float_as_uint(vp[0]);
                uint32_t b1 = __float_as_uint(vp[4 * VSTR]);
                mma_tf32(O[df], A, b0, b1);
            }
        }

        __syncthreads();
    }

    // ---- epilogue: normalize + write ----
    const float inv0 = 1.f / l0;
    const float inv1 = 1.f / l1;
    float* Op0 = AO + ((size_t)b * Ss + qrow) * 512 + h * 64;
    float* Op1 = Op0 + (size_t)8 * 512;
    #pragma unroll
    for (int df = 0; df < 8; df++) {
        float2 o0 = { O[df][0] * inv0, O[df][1] * inv0 };
        float2 o1 = { O[df][2] * inv1, O[df][3] * inv1 };
        *(float2*)(Op0 + df * 8 + 2 * tig) = o0;
        *(float2*)(Op1 + df * 8 + 2 * tig) = o1;
    }
}

// ===========================================================================
// Residual + LayerNorm
// ===========================================================================
__global__ __launch_bounds__(512)
void ln_kernel(const float* __restrict__ q, const float* __restrict__ gamma,
               const float* __restrict__ beta, float* __restrict__ out) {
    __shared__ float rs[16], rs2[16];
    const int r = blockIdx.x;
    const int j = threadIdx.x;

    const float v = q[(size_t)r * 512 + j] + g_P[(size_t)r * 512 + j];

    float s = v, s2 = v * v;
    #pragma unroll
    for (int o = 16; o > 0; o >>= 1) {
        s  += __shfl_xor_sync(0xffffffffu, s,  o);
        s2 += __shfl_xor_sync(0xffffffffu, s2, o);
    }
    const int w = j >> 5, ln = j & 31;
    if (ln == 0) { rs[w] = s; rs2[w] = s2; }
    __syncthreads();
    if (w == 0) {
        s  = (ln < 16) ? rs[ln]  : 0.f;
        s2 = (ln < 16) ? rs2[ln] : 0.f;
        #pragma unroll
        for (int o = 8; o > 0; o >>= 1) {
            s  += __shfl_xor_sync(0xffffffffu, s,  o);
            s2 += __shfl_xor_sync(0xffffffffu, s2, o);
        }
        if (ln == 0) { rs[0] = s; rs2[0] = s2; }
    }
    __syncthreads();

    const float mu  = rs[0] * (1.f / 512.f);
    const float var = rs2[0] * (1.f / 512.f) - mu * mu;
    const float inv = rsqrtf(var + 1e-5f);
    out[(size_t)r * 512 + j] = (v - mu) * inv * gamma[j] + beta[j];
}

// ===========================================================================
extern "C" void kernel_launch(void* const* d_in, const int* in_sizes, int n_in,
                              void* d_out, int out_size) {
    const float* q     = (const float*)d_in[0];
    const float* k     = (const float*)d_in[1];
    const float* v     = (const float*)d_in[2];
    const float* mask  = (const float*)d_in[3];
    const float* Wq    = (const float*)d_in[4];
    const float* bq    = (const float*)d_in[5];
    const float* Wk    = (const float*)d_in[6];
    const float* bk    = (const float*)d_in[7];
    const float* Wv    = (const float*)d_in[8];
    const float* bv    = (const float*)d_in[9];
    const float* Wo    = (const float*)d_in[10];
    const float* bo    = (const float*)d_in[11];
    const float* gamma = (const float*)d_in[12];
    const float* beta  = (const float*)d_in[13];
    float* out = (float*)d_out;

    float *gQ, *gK, *gV, *gAO, *gP;
    cudaGetSymbolAddress((void**)&gQ,  g_Q);
    cudaGetSymbolAddress((void**)&gK,  g_K);
    cudaGetSymbolAddress((void**)&gV,  g_V);
    cudaGetSymbolAddress((void**)&gAO, g_AO);
    cudaGetSymbolAddress((void**)&gP,  g_P);

    dim3 gg(MROWS / 128, 512 / 128);
    gemm_tc_kernel<<<gg, 256>>>(q, Wq, bq, gQ);
    gemm_tc_kernel<<<gg, 256>>>(k, Wk, bk, gK);
    gemm_tc_kernel<<<gg, 256>>>(v, Wv, bv, gV);

    attn_mma_kernel<<<dim3(Ss / 128, Bb * Hh), 256>>>(gQ, gK, gV, mask, gAO);

    gemm_tc_kernel<<<gg, 256>>>(gAO, Wo, bo, gP);

    ln_kernel<<<MROWS, 512>>>(q, gamma, beta, out);
}

// round 8
// speedup vs baseline: 7.3971x; 1.0640x over previous
#include <cuda_runtime.h>
#include <cstddef>
#include <cstdint>

#define Bb   4
#define Ss   2048
#define DIN  512
#define Hh   8
#define DM   512
#define MROWS (Bb*Ss)          // 8192

// Scratch (device globals: allocation-free rule)
__device__ float g_Q [MROWS*DM];
__device__ float g_K [MROWS*DM];
__device__ float g_V [MROWS*DM];
__device__ float g_AO[MROWS*DM];
__device__ float g_P [MROWS*DIN];

// ===========================================================================
// helpers
// ===========================================================================
__device__ __forceinline__ uint32_t f2tf32(float f) {
    uint32_t r;
    asm("cvt.rna.tf32.f32 %0, %1;" : "=r"(r) : "f"(f));
    return r;
}

// D += A * B  (m16n8k8, tf32 inputs, fp32 accum). row.col.
__device__ __forceinline__ void mma_tf32(float* d, const uint32_t* a,
                                         uint32_t b0, uint32_t b1) {
    asm volatile(
        "mma.sync.aligned.m16n8k8.row.col.f32.tf32.tf32.f32 "
        "{%0,%1,%2,%3}, {%4,%5,%6,%7}, {%8,%9}, {%0,%1,%2,%3};"
        : "+f"(d[0]), "+f"(d[1]), "+f"(d[2]), "+f"(d[3])
        : "r"(a[0]), "r"(a[1]), "r"(a[2]), "r"(a[3]), "r"(b0), "r"(b1));
}

__device__ __forceinline__ void ldsm_x4(uint32_t* r, uint32_t addr) {
    asm volatile("ldmatrix.sync.aligned.m8n8.x4.shared.b16 {%0,%1,%2,%3}, [%4];"
                 : "=r"(r[0]), "=r"(r[1]), "=r"(r[2]), "=r"(r[3]) : "r"(addr));
}

// ===========================================================================
// Tensor-core GEMM (proven R5 version, unchanged)
// ===========================================================================
#define XS_STR 36
#define WS_STR 136

__global__ __launch_bounds__(256)
void gemm_tc_kernel(const float* __restrict__ X, const float* __restrict__ W,
                    const float* __restrict__ bias, float* __restrict__ C) {
    __shared__ float Xs[128 * XS_STR];
    __shared__ float Ws[32 * WS_STR];

    const int tid  = threadIdx.x;
    const int lane = tid & 31;
    const int wid  = tid >> 5;
    const int gid  = lane >> 2;
    const int tig  = lane & 3;

    const int warp_m = wid >> 2;
    const int warp_n = wid & 3;
    const int m_base = warp_m * 64;
    const int n_base = warp_n * 32;

    const int bm = blockIdx.x * 128;
    const int bn = blockIdx.y * 128;

    float acc[4][4][4];
    #pragma unroll
    for (int mf = 0; mf < 4; mf++)
        #pragma unroll
        for (int nf = 0; nf < 4; nf++)
            #pragma unroll
            for (int c = 0; c < 4; c++) acc[mf][nf][c] = 0.f;

    for (int k0 = 0; k0 < 512; k0 += 32) {
        #pragma unroll
        for (int l = 0; l < 4; l++) {
            int e = tid + l * 256;
            int r = e >> 3, c4 = e & 7;
            float4 v = *(const float4*)(X + (size_t)(bm + r) * 512 + k0 + c4 * 4);
            uint4 t = { f2tf32(v.x), f2tf32(v.y), f2tf32(v.z), f2tf32(v.w) };
            *(uint4*)(Xs + r * XS_STR + c4 * 4) = t;
        }
        #pragma unroll
        for (int l = 0; l < 4; l++) {
            int e = tid + l * 256;
            int r = e >> 5, c4 = e & 31;
            float4 v = *(const float4*)(W + (size_t)(k0 + r) * 512 + bn + c4 * 4);
            uint4 t = { f2tf32(v.x), f2tf32(v.y), f2tf32(v.z), f2tf32(v.w) };
            *(uint4*)(Ws + r * WS_STR + c4 * 4) = t;
        }
        __syncthreads();

        #pragma unroll
        for (int ks = 0; ks < 4; ks++) {
            const int kk = ks * 8;
            uint32_t A[4][4];
            #pragma unroll
            for (int mf = 0; mf < 4; mf++) {
                const float* ap = Xs + (m_base + mf * 16 + gid) * XS_STR + kk + tig;
                A[mf][0] = __float_as_uint(ap[0]);
                A[mf][1] = __float_as_uint(ap[8 * XS_STR]);
                A[mf][2] = __float_as_uint(ap[4]);
                A[mf][3] = __float_as_uint(ap[8 * XS_STR + 4]);
            }
            #pragma unroll
            for (int nf = 0; nf < 4; nf++) {
                const float* bp = Ws + (kk + tig) * WS_STR + n_base + nf * 8 + gid;
                uint32_t b0 = __float_as_uint(bp[0]);
                uint32_t b1 = __float_as_uint(bp[4 * WS_STR]);
                #pragma unroll
                for (int mf = 0; mf < 4; mf++)
                    mma_tf32(acc[mf][nf], A[mf], b0, b1);
            }
        }
        __syncthreads();
    }

    #pragma unroll
    for (int nf = 0; nf < 4; nf++) {
        const int col = bn + n_base + nf * 8 + 2 * tig;
        float2 b2 = *(const float2*)(bias + col);
        #pragma unroll
        for (int mf = 0; mf < 4; mf++) {
            const int row0 = bm + m_base + mf * 16 + gid;
            float2 o0 = { acc[mf][nf][0] + b2.x, acc[mf][nf][1] + b2.y };
            float2 o1 = { acc[mf][nf][2] + b2.x, acc[mf][nf][3] + b2.y };
            *(float2*)(C + (size_t)row0 * 512 + col) = o0;
            *(float2*)(C + (size_t)(row0 + 8) * 512 + col) = o1;
        }
    }
}

// ===========================================================================
// mma.sync tf32 flash attention, v4.
// 1 CTA = (b,h), 128 q-rows, 4 warps x 32 q-rows (2 m16 frags per warp).
// Every K ldsm / V LDS feeds 2 MMAs -> operand smem traffic halved vs v3.
// 32-key tiles, double-buffered K/V; K via ldmatrix.x4; P stays in regs.
// ===========================================================================
#define KSTR 68
#define VSTR 72
#define SM_K0 0
#define SM_K1 (32*KSTR)
#define SM_V0 (2*32*KSTR)
#define SM_V1 (SM_V0 + 32*VSTR)
#define ATTN_SMEM_FLOATS (SM_V0 + 2*32*VSTR)   // 8960 floats = 35840 B

__global__ __launch_bounds__(128, 2)
void attn_mma_kernel(const float* __restrict__ Qg, const float* __restrict__ Kg,
                     const float* __restrict__ Vg, const float* __restrict__ mask,
                     float* __restrict__ AO) {
    __shared__ float sm[ATTN_SMEM_FLOATS];
    const int tid  = threadIdx.x;
    const int lane = tid & 31;
    const int wid  = tid >> 5;        // 0..3
    const int gid  = lane >> 2;
    const int tig  = lane & 3;
    const int srcA = (lane & ~3) | (tig >> 1);
    const int srcB = srcA + 2;
    const bool odd = (tig & 1);

    const int lm_base = (lane & 7) * KSTR + ((lane >> 3) & 1) * 4 + (lane >> 4) * 8;
    const uint32_t smK0_u = (uint32_t)__cvta_generic_to_shared(sm + SM_K0);
    const uint32_t smK1_u = (uint32_t)__cvta_generic_to_shared(sm + SM_K1);

    const int bh = blockIdx.y;
    const int b  = bh >> 3;
    const int h  = bh & 7;
    const int q0 = blockIdx.x * 128;

    const float* Kb = Kg + (size_t)b * Ss * 512 + h * 64;
    const float* Vb = Vg + (size_t)b * Ss * 512 + h * 64;

    // persistent Q A-fragments, two m16 frags per warp (pre-scaled 1/8, tf32)
    const int qrow0 = q0 + wid * 32 + gid;     // frag 0 base row
    const int qrow1 = qrow0 + 16;              // frag 1 base row
    uint32_t Qa[2][8][4];
    #pragma unroll
    for (int mf = 0; mf < 2; mf++) {
        const float* Qp = Qg + ((size_t)b * Ss + (mf ? qrow1 : qrow0)) * 512 + h * 64;
        #pragma unroll
        for (int ch = 0; ch < 8; ch++) {
            Qa[mf][ch][0] = f2tf32(Qp[ch * 8 + tig] * 0.125f);
            Qa[mf][ch][1] = f2tf32(Qp[8 * 512 + ch * 8 + tig] * 0.125f);
            Qa[mf][ch][2] = f2tf32(Qp[ch * 8 + tig + 4] * 0.125f);
            Qa[mf][ch][3] = f2tf32(Qp[8 * 512 + ch * 8 + tig + 4] * 0.125f);
        }
    }

    // K/V 32-key tile loader (128 threads)
    auto load_kv = [&](int k0, int sel) {
        float* Ks = sm + (sel ? SM_K1 : SM_K0);
        float* Vs = sm + (sel ? SM_V1 : SM_V0);
        #pragma unroll
        for (int l = 0; l < 4; l++) {
            int e = tid + l * 128;          // 0..511
            int r = e >> 4, c4 = e & 15;    // 32 rows x 16 float4
            float4 kv = *(const float4*)(Kb + (size_t)(k0 + r) * 512 + c4 * 4);
            uint4 tk = { f2tf32(kv.x), f2tf32(kv.y), f2tf32(kv.z), f2tf32(kv.w) };
            *(uint4*)(Ks + r * KSTR + c4 * 4) = tk;
            float4 vv = *(const float4*)(Vb + (size_t)(k0 + r) * 512 + c4 * 4);
            uint4 tv = { f2tf32(vv.x), f2tf32(vv.y), f2tf32(vv.z), f2tf32(vv.w) };
            *(uint4*)(Vs + r * VSTR + c4 * 4) = tv;
        }
    };

    load_kv(0, 0);

    // mask row pointers: frag0 rows (gid, gid+8), frag1 rows (gid+16, gid+24)
    const float* Mr[4];
    Mr[0] = mask + (size_t)b * Ss * Ss + (size_t)qrow0 * Ss;
    Mr[1] = Mr[0] + (size_t)8 * Ss;
    Mr[2] = mask + (size_t)b * Ss * Ss + (size_t)qrow1 * Ss;
    Mr[3] = Mr[2] + (size_t)8 * Ss;

    float mI[4] = {-1e30f, -1e30f, -1e30f, -1e30f};
    float lI[4] = {0.f, 0.f, 0.f, 0.f};
    float O[2][8][4];
    #pragma unroll
    for (int mf = 0; mf < 2; mf++)
        #pragma unroll
        for (int j = 0; j < 8; j++)
            #pragma unroll
            for (int c = 0; c < 4; c++) O[mf][j][c] = 0.f;

    __syncthreads();

    for (int kt = 0; kt < 64; kt++) {
        const int sel = kt & 1;
        const int k0  = kt * 32;
        const float* Vs = sm + (sel ? SM_V1 : SM_V0);
        const uint32_t smK_u = sel ? smK1_u : smK0_u;

        // ---- prefetch mask (latency hidden under S-MMAs) ----
        float2 mk[4][4];
        #pragma unroll
        for (int r = 0; r < 4; r++)
            #pragma unroll
            for (int kf = 0; kf < 4; kf++)
                mk[r][kf] = *(const float2*)(Mr[r] + k0 + kf * 8 + 2 * tig);

        // ---- S = Q K^T : each ldsm feeds both m-frags ----
        float S[2][4][4];
        #pragma unroll
        for (int mf = 0; mf < 2; mf++)
            #pragma unroll
            for (int kf = 0; kf < 4; kf++)
                #pragma unroll
                for (int c = 0; c < 4; c++) S[mf][kf][c] = 0.f;

        #pragma unroll
        for (int kf = 0; kf < 4; kf++) {
            #pragma unroll
            for (int ch2 = 0; ch2 < 4; ch2++) {
                uint32_t r[4];
                ldsm_x4(r, smK_u + 4u * (uint32_t)(kf * 8 * KSTR + ch2 * 16 + lm_base));
                mma_tf32(S[0][kf], Qa[0][2 * ch2],     r[0], r[1]);
                mma_tf32(S[0][kf], Qa[0][2 * ch2 + 1], r[2], r[3]);
                mma_tf32(S[1][kf], Qa[1][2 * ch2],     r[0], r[1]);
                mma_tf32(S[1][kf], Qa[1][2 * ch2 + 1], r[2], r[3]);
            }
        }

        // ---- prefetch next K/V tile (overlaps softmax below) ----
        if (kt < 63) load_kv(k0 + 32, sel ^ 1);

        // ---- mask * s, threshold, online softmax (per m-frag) ----
        float fscale[4];
        #pragma unroll
        for (int mf = 0; mf < 2; mf++) {
            const int rA = mf * 2, rB = mf * 2 + 1;
            float mx0 = mI[rA], mx1 = mI[rB];
            #pragma unroll
            for (int kf = 0; kf < 4; kf++) {
                float s0 = S[mf][kf][0] * mk[rA][kf].x;
                float s1 = S[mf][kf][1] * mk[rA][kf].y;
                float s2 = S[mf][kf][2] * mk[rB][kf].x;
                float s3 = S[mf][kf][3] * mk[rB][kf].y;
                s0 = (s0 > 0.f) ? s0 : -10000.f;
                s1 = (s1 > 0.f) ? s1 : -10000.f;
                s2 = (s2 > 0.f) ? s2 : -10000.f;
                s3 = (s3 > 0.f) ? s3 : -10000.f;
                S[mf][kf][0] = s0; S[mf][kf][1] = s1;
                S[mf][kf][2] = s2; S[mf][kf][3] = s3;
                mx0 = fmaxf(mx0, fmaxf(s0, s1));
                mx1 = fmaxf(mx1, fmaxf(s2, s3));
            }
            mx0 = fmaxf(mx0, __shfl_xor_sync(0xffffffffu, mx0, 1));
            mx0 = fmaxf(mx0, __shfl_xor_sync(0xffffffffu, mx0, 2));
            mx1 = fmaxf(mx1, __shfl_xor_sync(0xffffffffu, mx1, 1));
            mx1 = fmaxf(mx1, __shfl_xor_sync(0xffffffffu, mx1, 2));

            float f0 = __expf(mI[rA] - mx0);
            float f1 = __expf(mI[rB] - mx1);
            float sum0 = 0.f, sum1 = 0.f;
            #pragma unroll
            for (int kf = 0; kf < 4; kf++) {
                float p0 = __expf(S[mf][kf][0] - mx0);
                float p1 = __expf(S[mf][kf][1] - mx0);
                float p2 = __expf(S[mf][kf][2] - mx1);
                float p3 = __expf(S[mf][kf][3] - mx1);
                sum0 += p0 + p1;
                sum1 += p2 + p3;
                S[mf][kf][0] = __uint_as_float(f2tf32(p0));
                S[mf][kf][1] = __uint_as_float(f2tf32(p1));
                S[mf][kf][2] = __uint_as_float(f2tf32(p2));
                S[mf][kf][3] = __uint_as_float(f2tf32(p3));
            }
            sum0 += __shfl_xor_sync(0xffffffffu, sum0, 1);
            sum0 += __shfl_xor_sync(0xffffffffu, sum0, 2);
            sum1 += __shfl_xor_sync(0xffffffffu, sum1, 1);
            sum1 += __shfl_xor_sync(0xffffffffu, sum1, 2);

            lI[rA] = lI[rA] * f0 + sum0;  mI[rA] = mx0;
            lI[rB] = lI[rB] * f1 + sum1;  mI[rB] = mx1;
            fscale[rA] = f0; fscale[rB] = f1;

            #pragma unroll
            for (int j = 0; j < 8; j++) {
                O[mf][j][0] *= f0; O[mf][j][1] *= f0;
                O[mf][j][2] *= f1; O[mf][j][3] *= f1;
            }
        }

        // ---- O += P @ V : each V LDS feeds both m-frags ----
        #pragma unroll
        for (int kc = 0; kc < 4; kc++) {
            uint32_t A[2][4];
            #pragma unroll
            for (int mf = 0; mf < 2; mf++) {
                float x0 = __shfl_sync(0xffffffffu, S[mf][kc][0], srcA);
                float x1 = __shfl_sync(0xffffffffu, S[mf][kc][1], srcA);
                float y0 = __shfl_sync(0xffffffffu, S[mf][kc][2], srcA);
                float y1 = __shfl_sync(0xffffffffu, S[mf][kc][3], srcA);
                float z0 = __shfl_sync(0xffffffffu, S[mf][kc][0], srcB);
                float z1 = __shfl_sync(0xffffffffu, S[mf][kc][1], srcB);
                float w0 = __shfl_sync(0xffffffffu, S[mf][kc][2], srcB);
                float w1 = __shfl_sync(0xffffffffu, S[mf][kc][3], srcB);
                A[mf][0] = __float_as_uint(odd ? x1 : x0);
                A[mf][1] = __float_as_uint(odd ? y1 : y0);
                A[mf][2] = __float_as_uint(odd ? z1 : z0);
                A[mf][3] = __float_as_uint(odd ? w1 : w0);
            }
            #pragma unroll
            for (int df = 0; df < 8; df++) {
                const float* vp = Vs + (kc * 8 + tig) * VSTR + df * 8 + gid;
                uint32_t b0 = __float_as_uint(vp[0]);
                uint32_t b1 = __float_as_uint(vp[4 * VSTR]);
                mma_tf32(O[0][df], A[0], b0, b1);
                mma_tf32(O[1][df], A[1], b0, b1);
            }
        }

        __syncthreads();
    }

    // ---- epilogue: normalize + write (both frags) ----
    #pragma unroll
    for (int mf = 0; mf < 2; mf++) {
        const int rA = mf * 2, rB = mf * 2 + 1;
        const float inv0 = 1.f / lI[rA];
        const float inv1 = 1.f / lI[rB];
        float* Op0 = AO + ((size_t)b * Ss + (mf ? qrow1 : qrow0)) * 512 + h * 64;
        float* Op1 = Op0 + (size_t)8 * 512;
        #pragma unroll
        for (int df = 0; df < 8; df++) {
            float2 o0 = { O[mf][df][0] * inv0, O[mf][df][1] * inv0 };
            float2 o1 = { O[mf][df][2] * inv1, O[mf][df][3] * inv1 };
            *(float2*)(Op0 + df * 8 + 2 * tig) = o0;
            *(float2*)(Op1 + df * 8 + 2 * tig) = o1;
        }
    }
}

// ===========================================================================
// Residual + LayerNorm
// ===========================================================================
__global__ __launch_bounds__(512)
void ln_kernel(const float* __restrict__ q, const float* __restrict__ gamma,
               const float* __restrict__ beta, float* __restrict__ out) {
    __shared__ float rs[16], rs2[16];
    const int r = blockIdx.x;
    const int j = threadIdx.x;

    const float v = q[(size_t)r * 512 + j] + g_P[(size_t)r * 512 + j];

    float s = v, s2 = v * v;
    #pragma unroll
    for (int o = 16; o > 0; o >>= 1) {
        s  += __shfl_xor_sync(0xffffffffu, s,  o);
        s2 += __shfl_xor_sync(0xffffffffu, s2, o);
    }
    const int w = j >> 5, ln = j & 31;
    if (ln == 0) { rs[w] = s; rs2[w] = s2; }
    __syncthreads();
    if (w == 0) {
        s  = (ln < 16) ? rs[ln]  : 0.f;
        s2 = (ln < 16) ? rs2[ln] : 0.f;
        #pragma unroll
        for (int o = 8; o > 0; o >>= 1) {
            s  += __shfl_xor_sync(0xffffffffu, s,  o);
            s2 += __shfl_xor_sync(0xffffffffu, s2, o);
        }
        if (ln == 0) { rs[0] = s; rs2[0] = s2; }
    }
    __syncthreads();

    const float mu  = rs[0] * (1.f / 512.f);
    const float var = rs2[0] * (1.f / 512.f) - mu * mu;
    const float inv = rsqrtf(var + 1e-5f);
    out[(size_t)r * 512 + j] = (v - mu) * inv * gamma[j] + beta[j];
}

// ===========================================================================
extern "C" void kernel_launch(void* const* d_in, const int* in_sizes, int n_in,
                              void* d_out, int out_size) {
    const float* q     = (const float*)d_in[0];
    const float* k     = (const float*)d_in[1];
    const float* v     = (const float*)d_in[2];
    const float* mask  = (const float*)d_in[3];
    const float* Wq    = (const float*)d_in[4];
    const float* bq    = (const float*)d_in[5];
    const float* Wk    = (const float*)d_in[6];
    const float* bk    = (const float*)d_in[7];
    const float* Wv    = (const float*)d_in[8];
    const float* bv    = (const float*)d_in[9];
    const float* Wo    = (const float*)d_in[10];
    const float* bo    = (const float*)d_in[11];
    const float* gamma = (const float*)d_in[12];
    const float* beta  = (const float*)d_in[13];
    float* out = (float*)d_out;

    float *gQ, *gK, *gV, *gAO, *gP;
    cudaGetSymbolAddress((void**)&gQ,  g_Q);
    cudaGetSymbolAddress((void**)&gK,  g_K);
    cudaGetSymbolAddress((void**)&gV,  g_V);
    cudaGetSymbolAddress((void**)&gAO, g_AO);
    cudaGetSymbolAddress((void**)&gP,  g_P);

    dim3 gg(MROWS / 128, 512 / 128);
    gemm_tc_kernel<<<gg, 256>>>(q, Wq, bq, gQ);
    gemm_tc_kernel<<<gg, 256>>>(k, Wk, bk, gK);
    gemm_tc_kernel<<<gg, 256>>>(v, Wv, bv, gV);

    attn_mma_kernel<<<dim3(Ss / 128, Bb * Hh), 128>>>(gQ, gK, gV, mask, gAO);

    gemm_tc_kernel<<<gg, 256>>>(gAO, Wo, bo, gP);

    ln_kernel<<<MROWS, 512>>>(q, gamma, beta, out);
}